// round 13
// baseline (speedup 1.0000x reference)
#include <cuda_runtime.h>
#include <cuda_bf16.h>
#include <math.h>
#include <stdint.h>

// ---------------- problem constants ----------------
#define B_      2
#define L_      1024
#define V_      32000
#define H_      1024
#define INNER_  2048
#define S_      16
#define DT_     64
#define KC_     4
#define F_      2048
#define E_      8
#define T_      (B_*L_)          // 2048 tokens
#define P2_     (2*INNER_)       // 4096
#define XPW_    (DT_ + 2*S_)     // 96
#define EPS_    1e-5f
#define NPAD_   5120             // padded token-expert pairs (upper bound)
#define MT_MOE_ (NPAD_/128)      // 40 M-tiles max for MoE GEMMs

// ---------------- scratch (static device memory; no runtime alloc) ----------------
__device__ float g_x     [T_*H_];
__device__ float g_xn    [T_*H_];
__device__ float g_proj  [T_*P2_];
__device__ float g_uconv [T_*INNER_];
__device__ float g_xp    [T_*XPW_];
__device__ float g_delta [T_*INNER_];
__device__ float g_h1    [(size_t)NPAD_*P2_];
__device__ float g_moeout[(size_t)NPAD_*H_];
__device__ int   g_tope  [T_*2];
__device__ float g_topw  [T_*2];
__device__ int   g_cnt[E_], g_offp[E_];
__device__ int   g_pairtok[NPAD_];
__device__ float g_pairw [NPAD_];
__device__ int   g_pairpos[T_*2];
__device__ int   g_tile_expert[MT_MOE_];
__device__ int   g_pad_total;            // actual padded pair count (multiple of 128)

// bf16 hi|lo split buffers: row layout [hi(0..K-1) | lo(K..2K-1)], width 2K  (round-5 verified)
__device__ __nv_bfloat16 g_wa_in  [(size_t)P2_*2*H_];
__device__ __nv_bfloat16 g_wa_out [(size_t)H_*2*INNER_];
__device__ __nv_bfloat16 g_wa_fc1 [(size_t)E_*P2_*2*H_];
__device__ __nv_bfloat16 g_wa_fc2 [(size_t)E_*H_*2*F_];
__device__ __nv_bfloat16 g_wa_emb [(size_t)V_*2*H_];
__device__ __nv_bfloat16 g_a1     [(size_t)T_*2*H_];      // norm0 output, split
__device__ __nv_bfloat16 g_a_gu   [(size_t)T_*2*INNER_];  // y*silu(gate), split (written by scan)
__device__ __nv_bfloat16 g_a_pairs[(size_t)NPAD_*2*H_];
__device__ __nv_bfloat16 g_a_hid  [(size_t)NPAD_*2*F_];
__device__ __nv_bfloat16 g_a_fin  [(size_t)T_*2*H_];

// ---------------- device helpers ----------------
__device__ __forceinline__ float siluf(float x) { return x / (1.0f + __expf(-x)); }

__device__ __forceinline__ void bsplit(float x, unsigned short& h, unsigned short& l) {
    __nv_bfloat16 hb = __float2bfloat16(x);
    float hr = __bfloat162float(hb);
    __nv_bfloat16 lb = __float2bfloat16(x - hr);
    h = __bfloat16_as_ushort(hb);
    l = __bfloat16_as_ushort(lb);
}

__device__ __forceinline__ float block_reduce_sum_256(float v) {
    #pragma unroll
    for (int o = 16; o; o >>= 1) v += __shfl_xor_sync(0xffffffffu, v, o);
    __shared__ float sm[8];
    int w = threadIdx.x >> 5;
    if ((threadIdx.x & 31) == 0) sm[w] = v;
    __syncthreads();
    float r = (threadIdx.x < 8) ? sm[threadIdx.x] : 0.0f;
    if (threadIdx.x < 32) {
        #pragma unroll
        for (int o = 4; o; o >>= 1) r += __shfl_xor_sync(0xffffffffu, r, o);
    }
    return r;
}

// ---------------- generic PTX (sm_80-compatible) ----------------
__device__ __forceinline__ uint32_t smem_u32(const void* p) {
    uint32_t a;
    asm("{ .reg .u64 t; cvta.to.shared.u64 t, %1; cvt.u32.u64 %0, t; }" : "=r"(a) : "l"(p));
    return a;
}
__device__ __forceinline__ void cp16(uint32_t dst, const void* src) {
    asm volatile("cp.async.cg.shared.global [%0], [%1], 16;" :: "r"(dst), "l"(src) : "memory");
}
#define CP_COMMIT() asm volatile("cp.async.commit_group;" ::: "memory")
#define CP_WAIT1()  asm volatile("cp.async.wait_group 1;" ::: "memory")

__device__ __forceinline__ void ldsm4(uint32_t* r, uint32_t a) {
    asm volatile("ldmatrix.sync.aligned.m8n8.x4.shared.b16 {%0,%1,%2,%3}, [%4];"
                 : "=r"(r[0]), "=r"(r[1]), "=r"(r[2]), "=r"(r[3]) : "r"(a));
}
__device__ __forceinline__ void mma16816(float* c, const uint32_t* a, uint32_t b0, uint32_t b1) {
    asm volatile("mma.sync.aligned.m16n8k16.row.col.f32.bf16.bf16.f32 "
                 "{%0,%1,%2,%3}, {%4,%5,%6,%7}, {%8,%9}, {%0,%1,%2,%3};"
                 : "+f"(c[0]), "+f"(c[1]), "+f"(c[2]), "+f"(c[3])
                 : "r"(a[0]), "r"(a[1]), "r"(a[2]), "r"(a[3]), "r"(b0), "r"(b1));
}

// ---------------- single-phase bf16 tensor GEMM (round-4/5 verified core) ----------------
#define BKROW    40                        // padded smem row (bf16): 80 B
#define ROWB     (BKROW*2)
#define ASIZE    (128*ROWB)                // 10240 B
#define STGB     (2*ASIZE)                 // 20480 B
#define SMEM_MMA (3*STGB)                  // 61440 B

__global__ void __launch_bounds__(256, 1)
mma_gemm(const __nv_bfloat16* __restrict__ A, const __nv_bfloat16* __restrict__ B,
         float* __restrict__ C, int ldc, int Kel, int aoff, int boff,
         int accum, int moe, int nrowsB)
{
    const int mtile = blockIdx.x, ntile = blockIdx.y;
    if (moe && mtile * 128 >= g_pad_total) return;   // skip tiles beyond actual padded pairs

    extern __shared__ __align__(16) char smem[];
    uint32_t sb = smem_u32(smem);
    const int tid = threadIdx.x, lane = tid & 31, wid = tid >> 5;
    const int wm = wid >> 1, wn = wid & 1;
    const int lda = 2 * Kel;
    const int KT = Kel / 32;

    const __nv_bfloat16* Ag = A + (size_t)mtile * 128 * lda + aoff;
    const __nv_bfloat16* Bg = B + (size_t)ntile * 128 * lda + boff
                            + (moe ? (size_t)g_tile_expert[mtile] * nrowsB * lda : 0);

    const int lr = tid >> 2;
    const int lc = (tid & 3) * 8;

    float c[2][8][4];
    #pragma unroll
    for (int i = 0; i < 2; i++)
        #pragma unroll
        for (int j = 0; j < 8; j++)
            #pragma unroll
            for (int q = 0; q < 4; q++) c[i][j][q] = 0.0f;

    auto issue = [&](int kt, int stage) {
        uint32_t sA = sb + stage * STGB;
        uint32_t sB = sA + ASIZE;
        int ko = kt * 32;
        #pragma unroll
        for (int h = 0; h < 2; h++) {
            int row = lr + h * 64;
            cp16(sA + row * ROWB + lc * 2, Ag + (size_t)row * lda + ko + lc);
            cp16(sB + row * ROWB + lc * 2, Bg + (size_t)row * lda + ko + lc);
        }
    };

    issue(0, 0); CP_COMMIT();
    issue(1, 1); CP_COMMIT();

    const int lrow  = (lane & 15);
    const int lcolB = (lane >> 4) * 16;

    for (int kt = 0; kt < KT; kt++) {
        int stage = kt % 3;
        CP_WAIT1();
        __syncthreads();
        if (kt + 2 < KT) issue(kt + 2, (kt + 2) % 3);
        CP_COMMIT();

        uint32_t aB = sb + stage * STGB + (wm * 32) * ROWB;
        uint32_t bB = sb + stage * STGB + ASIZE + (wn * 64) * ROWB;
        #pragma unroll
        for (int ks = 0; ks < 2; ks++) {
            uint32_t kb = ks * 32 + lcolB;
            uint32_t a0[4], a1[4], b0[4], b1[4], b2[4], b3[4];
            ldsm4(a0, aB + lrow * ROWB + kb);
            ldsm4(a1, aB + (16 + lrow) * ROWB + kb);
            ldsm4(b0, bB + lrow * ROWB + kb);
            ldsm4(b1, bB + (16 + lrow) * ROWB + kb);
            ldsm4(b2, bB + (32 + lrow) * ROWB + kb);
            ldsm4(b3, bB + (48 + lrow) * ROWB + kb);
            #pragma unroll
            for (int m = 0; m < 2; m++) {
                const uint32_t* af = m ? a1 : a0;
                mma16816(c[m][0], af, b0[0], b0[2]);
                mma16816(c[m][1], af, b0[1], b0[3]);
                mma16816(c[m][2], af, b1[0], b1[2]);
                mma16816(c[m][3], af, b1[1], b1[3]);
                mma16816(c[m][4], af, b2[0], b2[2]);
                mma16816(c[m][5], af, b2[1], b2[3]);
                mma16816(c[m][6], af, b3[0], b3[2]);
                mma16816(c[m][7], af, b3[1], b3[3]);
            }
        }
    }

    const int row0 = mtile * 128 + wm * 32 + (lane >> 2);
    const int col0 = ntile * 128 + wn * 64 + (lane & 3) * 2;
    #pragma unroll
    for (int m = 0; m < 2; m++) {
        #pragma unroll
        for (int n = 0; n < 8; n++) {
            float* p0 = C + (size_t)(row0 + m * 16) * ldc + col0 + n * 8;
            float* p1 = p0 + 8 * (size_t)ldc;
            float2 v0 = make_float2(c[m][n][0], c[m][n][1]);
            float2 v1 = make_float2(c[m][n][2], c[m][n][3]);
            if (accum) {
                float2 o0 = *reinterpret_cast<float2*>(p0);
                float2 o1 = *reinterpret_cast<float2*>(p1);
                v0.x += o0.x; v0.y += o0.y; v1.x += o1.x; v1.y += o1.y;
            }
            *reinterpret_cast<float2*>(p0) = v0;
            *reinterpret_cast<float2*>(p1) = v1;
        }
    }
}

// ---------------- weight split: fp32 [N,K] -> bf16 [N, hi(K)|lo(K)] ----------------
__global__ void __launch_bounds__(256)
split_w_kernel(const float* __restrict__ src, __nv_bfloat16* __restrict__ dst, int K, int total4)
{
    int i = blockIdx.x * 256 + threadIdx.x;
    if (i >= total4) return;
    int k4n = K >> 2;
    int n = i / k4n;
    int k = (i - n * k4n) * 4;
    float4 v = reinterpret_cast<const float4*>(src)[i];
    ushort4 h, l;
    bsplit(v.x, h.x, l.x); bsplit(v.y, h.y, l.y); bsplit(v.z, h.z, l.z); bsplit(v.w, h.w, l.w);
    *reinterpret_cast<ushort4*>(&dst[(size_t)n * 2 * K + k])     = h;
    *reinterpret_cast<ushort4*>(&dst[(size_t)n * 2 * K + K + k]) = l;
}

// ---------------- fp32 SIMT GEMM (x_proj, dt_proj only) ----------------
#define SMPAD 68
__global__ void __launch_bounds__(256)
gemm_kernel(const float* __restrict__ A, int lda,
            const float* __restrict__ B, int ldb,
            float* __restrict__ C, int ldc,
            int M, int N, int Kd,
            const float* __restrict__ bias, int accum)
{
    __shared__ float As[16][SMPAD];
    __shared__ float Bs[16][SMPAD];
    const int tid = threadIdx.x;
    const int tx = tid & 15, ty = tid >> 4;
    const int m0 = blockIdx.y * 64, n0 = blockIdx.x * 64;
    const int lrow = tid >> 2, lk4 = (tid & 3) * 4;
    const int am = m0 + lrow;
    const bool avalid = (am < M);
    const int bn = n0 + lrow;
    const bool bvalid = (bn < N);

    float acc[4][4];
    #pragma unroll
    for (int i = 0; i < 4; i++)
        #pragma unroll
        for (int j = 0; j < 4; j++) acc[i][j] = 0.0f;

    for (int k0 = 0; k0 < Kd; k0 += 16) {
        float4 av = make_float4(0.f,0.f,0.f,0.f), bv = make_float4(0.f,0.f,0.f,0.f);
        if (avalid) av = *reinterpret_cast<const float4*>(&A[(size_t)am * lda + k0 + lk4]);
        if (bvalid) bv = *reinterpret_cast<const float4*>(&B[(size_t)bn * ldb + k0 + lk4]);
        __syncthreads();
        As[lk4+0][lrow]=av.x; As[lk4+1][lrow]=av.y; As[lk4+2][lrow]=av.z; As[lk4+3][lrow]=av.w;
        Bs[lk4+0][lrow]=bv.x; Bs[lk4+1][lrow]=bv.y; Bs[lk4+2][lrow]=bv.z; Bs[lk4+3][lrow]=bv.w;
        __syncthreads();
        #pragma unroll
        for (int k = 0; k < 16; k++) {
            float4 a = *reinterpret_cast<const float4*>(&As[k][ty*4]);
            float4 b = *reinterpret_cast<const float4*>(&Bs[k][tx*4]);
            acc[0][0]+=a.x*b.x; acc[0][1]+=a.x*b.y; acc[0][2]+=a.x*b.z; acc[0][3]+=a.x*b.w;
            acc[1][0]+=a.y*b.x; acc[1][1]+=a.y*b.y; acc[1][2]+=a.y*b.z; acc[1][3]+=a.y*b.w;
            acc[2][0]+=a.z*b.x; acc[2][1]+=a.z*b.y; acc[2][2]+=a.z*b.z; acc[2][3]+=a.z*b.w;
            acc[3][0]+=a.w*b.x; acc[3][1]+=a.w*b.y; acc[3][2]+=a.w*b.z; acc[3][3]+=a.w*b.w;
        }
    }
    #pragma unroll
    for (int i = 0; i < 4; i++) {
        int cm = m0 + ty * 4 + i;
        if (cm >= M) continue;
        #pragma unroll
        for (int j = 0; j < 4; j++) {
            int n = n0 + tx * 4 + j;
            if (n >= N) continue;
            float v = acc[i][j];
            if (bias) v += bias[n];
            size_t ci = (size_t)cm * ldc + n;
            if (accum) C[ci] += v; else C[ci] = v;
        }
    }
}

// ---------------- pipeline kernels ----------------

// embed + norm0: writes g_x (raw) and split bf16 a1
__global__ void __launch_bounds__(256)
embed_rms_kernel(const int* __restrict__ ids, const float* __restrict__ emb,
                 const float* __restrict__ w)
{
    int t = blockIdx.x, tid = threadIdx.x;
    const float* er = emb + (size_t)ids[t] * H_;
    float v[4]; float ss = 0.0f;
    #pragma unroll
    for (int q = 0; q < 4; q++) {
        int i = tid + q * 256;
        v[q] = er[i];
        ss += v[q] * v[q];
        g_x[(size_t)t * H_ + i] = v[q];
    }
    ss = block_reduce_sum_256(ss);
    __shared__ float s_scale;
    if (tid == 0) s_scale = rsqrtf(ss * (1.0f / H_) + EPS_);
    __syncthreads();
    float sc = s_scale;
    #pragma unroll
    for (int q = 0; q < 4; q++) {
        int i = tid + q * 256;
        unsigned short h, l;
        bsplit(v[q] * sc * w[i], h, l);
        g_a1[(size_t)t * 2 * H_ + i]      = __ushort_as_bfloat16(h);
        g_a1[(size_t)t * 2 * H_ + H_ + i] = __ushort_as_bfloat16(l);
    }
}

__global__ void __launch_bounds__(256)
rms_kernel(const float* __restrict__ w)
{
    int t = blockIdx.x, tid = threadIdx.x;
    float v[4]; float ss = 0.0f;
    #pragma unroll
    for (int q = 0; q < 4; q++) { int i = tid + q*256; v[q] = g_x[(size_t)t*H_ + i]; ss += v[q]*v[q]; }
    ss = block_reduce_sum_256(ss);
    __shared__ float s_scale;
    if (tid == 0) s_scale = rsqrtf(ss * (1.0f / H_) + EPS_);
    __syncthreads();
    float sc = s_scale;
    #pragma unroll
    for (int q = 0; q < 4; q++) { int i = tid + q*256; g_xn[(size_t)t*H_ + i] = v[q] * sc * w[i]; }
}

__global__ void __launch_bounds__(256)
conv_silu_kernel(const float* __restrict__ cw, const float* __restrict__ cb)
{
    int idx = blockIdx.x * 256 + threadIdx.x;
    if (idx >= T_ * INNER_) return;
    int t = idx >> 11, c = idx & (INNER_ - 1);
    int b = t >> 10, l = t & (L_ - 1);
    float acc = cb[c];
    #pragma unroll
    for (int k = 0; k < KC_; k++) {
        int ll = l - (KC_ - 1) + k;
        if (ll >= 0) acc += g_proj[(size_t)((b << 10) + ll) * P2_ + c] * cw[c * KC_ + k];
    }
    g_uconv[idx] = siluf(acc);
}

// mamba scan, with fused gate multiply + split write (lane 0 of each 16-lane group)
__global__ void __launch_bounds__(256)
scan_kernel(const float* __restrict__ a_log, const float* __restrict__ d_param)
{
    int gid = blockIdx.x * 256 + threadIdx.x;
    int grp = gid >> 4, s = gid & 15;
    int b = grp >> 11, c = grp & (INNER_ - 1);
    const float LOG2E = 1.44269504088896340736f;
    float alog2 = -__expf(a_log[c * S_ + s]) * LOG2E;
    float dval = d_param[c];
    float st = 0.0f;
    int tbase = b * L_;
    for (int l = 0; l < L_; l++) {
        int t = tbase + l;
        float draw = g_delta[(size_t)t * INNER_ + c];
        float u = g_uconv[(size_t)t * INNER_ + c];
        float dl = (draw > 20.0f) ? draw : __logf(1.0f + __expf(draw));
        float bt = g_xp[t * XPW_ + DT_ + s];
        float ct = g_xp[t * XPW_ + DT_ + S_ + s];
        float decay = exp2f(dl * alog2);
        st = decay * st + (dl * u) * bt;
        float part = st * ct;
        part += __shfl_xor_sync(0xffffffffu, part, 8);
        part += __shfl_xor_sync(0xffffffffu, part, 4);
        part += __shfl_xor_sync(0xffffffffu, part, 2);
        part += __shfl_xor_sync(0xffffffffu, part, 1);
        if (s == 0) {
            float y = part + u * dval;
            float g = g_proj[(size_t)t * P2_ + INNER_ + c];
            float v = y * siluf(g);
            unsigned short h, lo;
            bsplit(v, h, lo);
            g_a_gu[(size_t)t * 2 * INNER_ + c]          = __ushort_as_bfloat16(h);
            g_a_gu[(size_t)t * 2 * INNER_ + INNER_ + c] = __ushort_as_bfloat16(lo);
        }
    }
}

__global__ void __launch_bounds__(256)
router_kernel(const float* __restrict__ rw, const float* __restrict__ rb)
{
    int t = blockIdx.x, tid = threadIdx.x;
    float part[E_];
    #pragma unroll
    for (int e = 0; e < E_; e++) part[e] = 0.0f;
    const float* xr = g_xn + (size_t)t * H_;
    for (int i = tid; i < H_; i += 256) {
        float xv = xr[i];
        #pragma unroll
        for (int e = 0; e < E_; e++) part[e] += xv * rw[e * H_ + i];
    }
    #pragma unroll
    for (int e = 0; e < E_; e++) {
        #pragma unroll
        for (int o = 16; o; o >>= 1) part[e] += __shfl_xor_sync(0xffffffffu, part[e], o);
    }
    __shared__ float red[8][E_];
    int w = tid >> 5;
    if ((tid & 31) == 0) {
        #pragma unroll
        for (int e = 0; e < E_; e++) red[w][e] = part[e];
    }
    __syncthreads();
    if (tid == 0) {
        float lg[E_];
        #pragma unroll
        for (int e = 0; e < E_; e++) {
            float s = 0.0f;
            #pragma unroll
            for (int ww = 0; ww < 8; ww++) s += red[ww][e];
            lg[e] = s + rb[e];
        }
        float mx = lg[0];
        #pragma unroll
        for (int e = 1; e < E_; e++) mx = fmaxf(mx, lg[e]);
        float p[E_], psum = 0.0f;
        #pragma unroll
        for (int e = 0; e < E_; e++) { p[e] = expf(lg[e] - mx); psum += p[e]; }
        float inv = 1.0f / psum;
        #pragma unroll
        for (int e = 0; e < E_; e++) p[e] *= inv;
        int i1 = 0;
        #pragma unroll
        for (int e = 1; e < E_; e++) if (p[e] > p[i1]) i1 = e;
        int i2 = (i1 == 0) ? 1 : 0;
        #pragma unroll
        for (int e = 0; e < E_; e++) if (e != i1 && p[e] > p[i2]) i2 = e;
        g_tope[t*2+0] = i1; g_tope[t*2+1] = i2;
        g_topw[t*2+0] = p[i1]; g_topw[t*2+1] = p[i2];
    }
}

// fused count + offsets + scatter: single CTA, 256 threads
__global__ void __launch_bounds__(256)
route_pack_kernel()
{
    __shared__ int scnt[E_], soff[E_], spos[E_];
    int tid = threadIdx.x;
    if (tid < E_) scnt[tid] = 0;
    __syncthreads();
    for (int t = tid; t < T_; t += 256) {
        atomicAdd(&scnt[g_tope[t*2+0]], 1);
        atomicAdd(&scnt[g_tope[t*2+1]], 1);
    }
    __syncthreads();
    if (tid == 0) {
        int a = 0;
        for (int e = 0; e < E_; e++) {
            soff[e] = a;
            g_offp[e] = a;
            g_cnt[e] = scnt[e];
            int pe = ((scnt[e] + 127) >> 7) << 7;
            int t0 = a >> 7, t1 = (a + pe) >> 7;
            for (int t = t0; t < t1; t++) g_tile_expert[t] = e;
            a += pe;
            spos[e] = 0;
        }
        g_pad_total = a;
        for (int t = a >> 7; t < MT_MOE_; t++) g_tile_expert[t] = 0;
    }
    __syncthreads();
    for (int t = tid; t < T_; t += 256) {
        #pragma unroll
        for (int j = 0; j < 2; j++) {
            int e = g_tope[t*2+j];
            int p = soff[e] + atomicAdd(&spos[e], 1);
            g_pairtok[p] = t;
            g_pairw[p] = g_topw[t*2+j];
            g_pairpos[t*2+j] = p;
        }
    }
}

__global__ void __launch_bounds__(256)
gather_pairs_kernel()
{
    int idx = blockIdx.x * 256 + threadIdx.x;
    int p = idx >> 8;
    int k = (idx & 255) * 4;
    int e = g_tile_expert[p >> 7];
    unsigned lcl = (unsigned)(p - g_offp[e]);
    ushort4 h = make_ushort4(0,0,0,0), l = make_ushort4(0,0,0,0);
    if (lcl < (unsigned)g_cnt[e]) {
        int tok = g_pairtok[p];
        float4 v = reinterpret_cast<const float4*>(g_xn)[(size_t)tok * (H_/4) + (k >> 2)];
        bsplit(v.x, h.x, l.x); bsplit(v.y, h.y, l.y); bsplit(v.z, h.z, l.z); bsplit(v.w, h.w, l.w);
    }
    *reinterpret_cast<ushort4*>(&g_a_pairs[(size_t)p * 2 * H_ + k])      = h;
    *reinterpret_cast<ushort4*>(&g_a_pairs[(size_t)p * 2 * H_ + H_ + k]) = l;
}

__global__ void __launch_bounds__(256)
hidden_split_kernel()
{
    int idx = blockIdx.x * 256 + threadIdx.x;
    if (idx >= NPAD_ * F_) return;
    int p = idx >> 11, f = idx & (F_ - 1);
    if (p >= g_pad_total) return;       // rows beyond padded total are never consumed
    float a = g_h1[(size_t)p * P2_ + f];
    float b2 = g_h1[(size_t)p * P2_ + F_ + f];
    float v = siluf(a) * b2;
    unsigned short h, l;
    bsplit(v, h, l);
    g_a_hid[(size_t)p * 2 * F_ + f]      = __ushort_as_bfloat16(h);
    g_a_hid[(size_t)p * 2 * F_ + F_ + f] = __ushort_as_bfloat16(l);
}

// fused: x += moe combine, then final RMSNorm -> split bf16 a_fin
__global__ void __launch_bounds__(256)
combine_rms_split_kernel(const float* __restrict__ w)
{
    int t = blockIdx.x, tid = threadIdx.x;
    int p0 = g_pairpos[t*2+0], p1 = g_pairpos[t*2+1];
    float w0 = g_pairw[p0], w1 = g_pairw[p1];
    float v[4]; float ss = 0.0f;
    #pragma unroll
    for (int q = 0; q < 4; q++) {
        int i = tid + q*256;
        float xv = g_x[(size_t)t*H_ + i]
                 + w0 * g_moeout[(size_t)p0 * H_ + i]
                 + w1 * g_moeout[(size_t)p1 * H_ + i];
        v[q] = xv;
        ss += xv * xv;
    }
    ss = block_reduce_sum_256(ss);
    __shared__ float s_scale;
    if (tid == 0) s_scale = rsqrtf(ss * (1.0f / H_) + EPS_);
    __syncthreads();
    float sc = s_scale;
    #pragma unroll
    for (int q = 0; q < 4; q++) {
        int i = tid + q*256;
        unsigned short h, l;
        bsplit(v[q] * sc * w[i], h, l);
        g_a_fin[(size_t)t * 2 * H_ + i]      = __ushort_as_bfloat16(h);
        g_a_fin[(size_t)t * 2 * H_ + H_ + i] = __ushort_as_bfloat16(l);
    }
}

// ---------------- host orchestration ----------------
extern "C" void kernel_launch(void* const* d_in, const int* in_sizes, int n_in,
                              void* d_out, int out_size)
{
    const int*   ids   = (const int*)  d_in[0];
    const float* emb   = (const float*)d_in[1];
    const float* n0w   = (const float*)d_in[2];
    const float* inpw  = (const float*)d_in[3];
    const float* convw = (const float*)d_in[4];
    const float* convb = (const float*)d_in[5];
    const float* xpw   = (const float*)d_in[6];
    const float* dtw   = (const float*)d_in[7];
    const float* dtb   = (const float*)d_in[8];
    const float* alog  = (const float*)d_in[9];
    const float* dpar  = (const float*)d_in[10];
    const float* outw  = (const float*)d_in[11];
    const float* n1w   = (const float*)d_in[12];
    const float* rw    = (const float*)d_in[13];
    const float* rb    = (const float*)d_in[14];
    const float* fc1   = (const float*)d_in[15];
    const float* fc2   = (const float*)d_in[16];
    const float* nfw   = (const float*)d_in[17];
    float* out = (float*)d_out;

    float *p_x, *p_xn, *p_proj, *p_uconv, *p_xp, *p_delta, *p_h1, *p_moeout;
    __nv_bfloat16 *p_wa_in, *p_wa_out, *p_wa_fc1, *p_wa_fc2, *p_wa_emb;
    __nv_bfloat16 *p_a1, *p_a_gu, *p_a_pairs, *p_a_hid, *p_a_fin;
    cudaGetSymbolAddress((void**)&p_x,      g_x);
    cudaGetSymbolAddress((void**)&p_xn,     g_xn);
    cudaGetSymbolAddress((void**)&p_proj,   g_proj);
    cudaGetSymbolAddress((void**)&p_uconv,  g_uconv);
    cudaGetSymbolAddress((void**)&p_xp,     g_xp);
    cudaGetSymbolAddress((void**)&p_delta,  g_delta);
    cudaGetSymbolAddress((void**)&p_h1,     g_h1);
    cudaGetSymbolAddress((void**)&p_moeout, g_moeout);
    cudaGetSymbolAddress((void**)&p_wa_in,  g_wa_in);
    cudaGetSymbolAddress((void**)&p_wa_out, g_wa_out);
    cudaGetSymbolAddress((void**)&p_wa_fc1, g_wa_fc1);
    cudaGetSymbolAddress((void**)&p_wa_fc2, g_wa_fc2);
    cudaGetSymbolAddress((void**)&p_wa_emb, g_wa_emb);
    cudaGetSymbolAddress((void**)&p_a1,     g_a1);
    cudaGetSymbolAddress((void**)&p_a_gu,   g_a_gu);
    cudaGetSymbolAddress((void**)&p_a_pairs,g_a_pairs);
    cudaGetSymbolAddress((void**)&p_a_hid,  g_a_hid);
    cudaGetSymbolAddress((void**)&p_a_fin,  g_a_fin);

    cudaFuncSetAttribute(mma_gemm, cudaFuncAttributeMaxDynamicSharedMemorySize, SMEM_MMA);

    // ---- weight hi/lo splits ----
    split_w_kernel<<<(P2_*H_/4 + 255)/256, 256>>>(inpw, p_wa_in,  H_,     P2_*H_/4);
    split_w_kernel<<<(H_*INNER_/4 + 255)/256, 256>>>(outw, p_wa_out, INNER_, H_*INNER_/4);
    split_w_kernel<<<(E_*P2_*H_/4 + 255)/256, 256>>>(fc1, p_wa_fc1, H_, E_*P2_*H_/4);
    split_w_kernel<<<(E_*H_*F_/4 + 255)/256, 256>>>(fc2, p_wa_fc2, F_, E_*H_*F_/4);
    split_w_kernel<<<(V_*H_/4 + 255)/256, 256>>>(emb, p_wa_emb, H_, V_*H_/4);

    // ---- pipeline ----
    embed_rms_kernel<<<T_, 256>>>(ids, emb, n0w);

    // in_proj (mma, 3 phases): [2048 x 4096], K=1024
    {
        dim3 g(T_/128, P2_/128);
        mma_gemm<<<g, 256, SMEM_MMA>>>(p_a1, p_wa_in, p_proj, P2_, H_, 0,  0,  0, 0, 0);
        mma_gemm<<<g, 256, SMEM_MMA>>>(p_a1, p_wa_in, p_proj, P2_, H_, H_, 0,  1, 0, 0);
        mma_gemm<<<g, 256, SMEM_MMA>>>(p_a1, p_wa_in, p_proj, P2_, H_, 0,  H_, 1, 0, 0);
    }

    conv_silu_kernel<<<(T_*INNER_ + 255)/256, 256>>>(convw, convb);

    // x_proj (SIMT): [2048 x 96], K=2048
    gemm_kernel<<<dim3((XPW_+63)/64, T_/64), 256>>>(p_uconv, INNER_, xpw, INNER_, p_xp, XPW_,
                                                    T_, XPW_, INNER_, nullptr, 0);
    // dt_proj (SIMT): [2048 x 2048], K=64
    gemm_kernel<<<dim3(INNER_/64, T_/64), 256>>>(p_xp, XPW_, dtw, DT_, p_delta, INNER_,
                                                 T_, INNER_, DT_, dtb, 0);

    // scan + fused gate multiply -> a_gu (split)
    scan_kernel<<<(B_*INNER_*S_)/256, 256>>>(alog, dpar);

    // out_proj (mma, 3 phases, accumulate into residual): [2048 x 1024], K=2048
    {
        dim3 g(T_/128, H_/128);
        mma_gemm<<<g, 256, SMEM_MMA>>>(p_a_gu, p_wa_out, p_x, H_, INNER_, 0,      0,      1, 0, 0);
        mma_gemm<<<g, 256, SMEM_MMA>>>(p_a_gu, p_wa_out, p_x, H_, INNER_, INNER_, 0,      1, 0, 0);
        mma_gemm<<<g, 256, SMEM_MMA>>>(p_a_gu, p_wa_out, p_x, H_, INNER_, 0,      INNER_, 1, 0, 0);
    }

    rms_kernel<<<T_, 256>>>(n1w);

    router_kernel<<<T_, 256>>>(rw, rb);
    route_pack_kernel<<<1, 256>>>();
    gather_pairs_kernel<<<(NPAD_*256 + 255)/256, 256>>>();

    // fc1 (mma, grouped, 3 phases, early-exit past padded total): [<=5120 x 4096], K=1024
    {
        dim3 g(MT_MOE_, P2_/128);
        mma_gemm<<<g, 256, SMEM_MMA>>>(p_a_pairs, p_wa_fc1, p_h1, P2_, H_, 0,  0,  0, 1, P2_);
        mma_gemm<<<g, 256, SMEM_MMA>>>(p_a_pairs, p_wa_fc1, p_h1, P2_, H_, H_, 0,  1, 1, P2_);
        mma_gemm<<<g, 256, SMEM_MMA>>>(p_a_pairs, p_wa_fc1, p_h1, P2_, H_, 0,  H_, 1, 1, P2_);
    }

    hidden_split_kernel<<<(NPAD_*F_ + 255)/256, 256>>>();

    // fc2 (mma, grouped, 3 phases, early-exit): [<=5120 x 1024], K=2048
    {
        dim3 g(MT_MOE_, H_/128);
        mma_gemm<<<g, 256, SMEM_MMA>>>(p_a_hid, p_wa_fc2, p_moeout, H_, F_, 0,  0,  0, 1, H_);
        mma_gemm<<<g, 256, SMEM_MMA>>>(p_a_hid, p_wa_fc2, p_moeout, H_, F_, F_, 0,  1, 1, H_);
        mma_gemm<<<g, 256, SMEM_MMA>>>(p_a_hid, p_wa_fc2, p_moeout, H_, F_, 0,  F_, 1, 1, H_);
    }

    // fused combine + final norm -> a_fin (split)
    combine_rms_split_kernel<<<T_, 256>>>(nfw);

    // logits (mma, 3 phases): [2048 x 32000], K=1024
    {
        dim3 g(T_/128, V_/128);
        mma_gemm<<<g, 256, SMEM_MMA>>>(p_a_fin, p_wa_emb, out, V_, H_, 0,  0,  0, 0, 0);
        mma_gemm<<<g, 256, SMEM_MMA>>>(p_a_fin, p_wa_emb, out, V_, H_, H_, 0,  1, 0, 0);
        mma_gemm<<<g, 256, SMEM_MMA>>>(p_a_fin, p_wa_emb, out, V_, H_, 0,  H_, 1, 0, 0);
    }
}

// round 14
// speedup vs baseline: 1.1249x; 1.1249x over previous
#include <cuda_runtime.h>
#include <cuda_bf16.h>
#include <math.h>
#include <stdint.h>

// ---------------- problem constants ----------------
#define B_      2
#define L_      1024
#define V_      32000
#define H_      1024
#define INNER_  2048
#define S_      16
#define DT_     64
#define KC_     4
#define F_      2048
#define E_      8
#define T_      (B_*L_)          // 2048 tokens
#define P2_     (2*INNER_)       // 4096
#define XPW_    (DT_ + 2*S_)     // 96
#define EPS_    1e-5f
#define NPAD_   5120             // padded token-expert pairs (upper bound)
#define MT_MOE_ (NPAD_/128)      // 40 M-tiles max for MoE GEMMs

// ---------------- scratch (static device memory; no runtime alloc) ----------------
__device__ float g_x     [T_*H_];
__device__ float g_xn    [T_*H_];
__device__ float g_proj  [T_*P2_];
__device__ float g_uconv [T_*INNER_];
__device__ float g_xp    [T_*XPW_];
__device__ float g_delta [T_*INNER_];
__device__ float g_y     [T_*INNER_];
__device__ float g_h1    [(size_t)NPAD_*P2_];
__device__ float g_moeout[(size_t)NPAD_*H_];
__device__ int   g_tope  [T_*2];
__device__ float g_topw  [T_*2];
__device__ int   g_cnt[E_], g_offp[E_];
__device__ int   g_pairtok[NPAD_];
__device__ float g_pairw [NPAD_];
__device__ int   g_pairpos[T_*2];
__device__ int   g_tile_expert[MT_MOE_];
__device__ int   g_pad_total;            // actual padded pair count (multiple of 128)

// bf16 hi|lo split buffers: row layout [hi(0..K-1) | lo(K..2K-1)], width 2K  (round-5 verified)
__device__ __nv_bfloat16 g_wa_in  [(size_t)P2_*2*H_];
__device__ __nv_bfloat16 g_wa_out [(size_t)H_*2*INNER_];
__device__ __nv_bfloat16 g_wa_fc1 [(size_t)E_*P2_*2*H_];
__device__ __nv_bfloat16 g_wa_fc2 [(size_t)E_*H_*2*F_];
__device__ __nv_bfloat16 g_wa_emb [(size_t)V_*2*H_];
__device__ __nv_bfloat16 g_a1     [(size_t)T_*2*H_];      // norm0 output, split
__device__ __nv_bfloat16 g_a_gu   [(size_t)T_*2*INNER_];  // y*silu(gate), split
__device__ __nv_bfloat16 g_a_pairs[(size_t)NPAD_*2*H_];
__device__ __nv_bfloat16 g_a_hid  [(size_t)NPAD_*2*F_];
__device__ __nv_bfloat16 g_a_fin  [(size_t)T_*2*H_];

// ---------------- device helpers ----------------
__device__ __forceinline__ float siluf(float x) { return x / (1.0f + __expf(-x)); }

__device__ __forceinline__ void bsplit(float x, unsigned short& h, unsigned short& l) {
    __nv_bfloat16 hb = __float2bfloat16(x);
    float hr = __bfloat162float(hb);
    __nv_bfloat16 lb = __float2bfloat16(x - hr);
    h = __bfloat16_as_ushort(hb);
    l = __bfloat16_as_ushort(lb);
}

__device__ __forceinline__ float block_reduce_sum_256(float v) {
    #pragma unroll
    for (int o = 16; o; o >>= 1) v += __shfl_xor_sync(0xffffffffu, v, o);
    __shared__ float sm[8];
    int w = threadIdx.x >> 5;
    if ((threadIdx.x & 31) == 0) sm[w] = v;
    __syncthreads();
    float r = (threadIdx.x < 8) ? sm[threadIdx.x] : 0.0f;
    if (threadIdx.x < 32) {
        #pragma unroll
        for (int o = 4; o; o >>= 1) r += __shfl_xor_sync(0xffffffffu, r, o);
    }
    return r;
}

// ---------------- generic PTX (sm_80-compatible) ----------------
__device__ __forceinline__ uint32_t smem_u32(const void* p) {
    uint32_t a;
    asm("{ .reg .u64 t; cvta.to.shared.u64 t, %1; cvt.u32.u64 %0, t; }" : "=r"(a) : "l"(p));
    return a;
}
__device__ __forceinline__ void cp16(uint32_t dst, const void* src) {
    asm volatile("cp.async.cg.shared.global [%0], [%1], 16;" :: "r"(dst), "l"(src) : "memory");
}
#define CP_COMMIT() asm volatile("cp.async.commit_group;" ::: "memory")
#define CP_WAIT1()  asm volatile("cp.async.wait_group 1;" ::: "memory")

__device__ __forceinline__ void ldsm4(uint32_t* r, uint32_t a) {
    asm volatile("ldmatrix.sync.aligned.m8n8.x4.shared.b16 {%0,%1,%2,%3}, [%4];"
                 : "=r"(r[0]), "=r"(r[1]), "=r"(r[2]), "=r"(r[3]) : "r"(a));
}
__device__ __forceinline__ void mma16816(float* c, const uint32_t* a, uint32_t b0, uint32_t b1) {
    asm volatile("mma.sync.aligned.m16n8k16.row.col.f32.bf16.bf16.f32 "
                 "{%0,%1,%2,%3}, {%4,%5,%6,%7}, {%8,%9}, {%0,%1,%2,%3};"
                 : "+f"(c[0]), "+f"(c[1]), "+f"(c[2]), "+f"(c[3])
                 : "r"(a[0]), "r"(a[1]), "r"(a[2]), "r"(a[3]), "r"(b0), "r"(b1));
}

// ---------------- single-phase bf16 tensor GEMM (round-4/5 verified core) ----------------
#define BKROW    40                        // padded smem row (bf16): 80 B
#define ROWB     (BKROW*2)
#define ASIZE    (128*ROWB)                // 10240 B
#define STGB     (2*ASIZE)                 // 20480 B
#define SMEM_MMA (3*STGB)                  // 61440 B

__global__ void __launch_bounds__(256, 1)
mma_gemm(const __nv_bfloat16* __restrict__ A, const __nv_bfloat16* __restrict__ B,
         float* __restrict__ C, int ldc, int Kel, int aoff, int boff,
         int accum, int moe, int nrowsB)
{
    const int mtile = blockIdx.x, ntile = blockIdx.y;
    if (moe && mtile * 128 >= g_pad_total) return;   // skip tiles beyond actual padded pairs

    extern __shared__ __align__(16) char smem[];
    uint32_t sb = smem_u32(smem);
    const int tid = threadIdx.x, lane = tid & 31, wid = tid >> 5;
    const int wm = wid >> 1, wn = wid & 1;
    const int lda = 2 * Kel;
    const int KT = Kel / 32;

    const __nv_bfloat16* Ag = A + (size_t)mtile * 128 * lda + aoff;
    const __nv_bfloat16* Bg = B + (size_t)ntile * 128 * lda + boff
                            + (moe ? (size_t)g_tile_expert[mtile] * nrowsB * lda : 0);

    const int lr = tid >> 2;
    const int lc = (tid & 3) * 8;

    float c[2][8][4];
    #pragma unroll
    for (int i = 0; i < 2; i++)
        #pragma unroll
        for (int j = 0; j < 8; j++)
            #pragma unroll
            for (int q = 0; q < 4; q++) c[i][j][q] = 0.0f;

    auto issue = [&](int kt, int stage) {
        uint32_t sA = sb + stage * STGB;
        uint32_t sB = sA + ASIZE;
        int ko = kt * 32;
        #pragma unroll
        for (int h = 0; h < 2; h++) {
            int row = lr + h * 64;
            cp16(sA + row * ROWB + lc * 2, Ag + (size_t)row * lda + ko + lc);
            cp16(sB + row * ROWB + lc * 2, Bg + (size_t)row * lda + ko + lc);
        }
    };

    issue(0, 0); CP_COMMIT();
    issue(1, 1); CP_COMMIT();

    const int lrow  = (lane & 15);
    const int lcolB = (lane >> 4) * 16;

    for (int kt = 0; kt < KT; kt++) {
        int stage = kt % 3;
        CP_WAIT1();
        __syncthreads();
        if (kt + 2 < KT) issue(kt + 2, (kt + 2) % 3);
        CP_COMMIT();

        uint32_t aB = sb + stage * STGB + (wm * 32) * ROWB;
        uint32_t bB = sb + stage * STGB + ASIZE + (wn * 64) * ROWB;
        #pragma unroll
        for (int ks = 0; ks < 2; ks++) {
            uint32_t kb = ks * 32 + lcolB;
            uint32_t a0[4], a1[4], b0[4], b1[4], b2[4], b3[4];
            ldsm4(a0, aB + lrow * ROWB + kb);
            ldsm4(a1, aB + (16 + lrow) * ROWB + kb);
            ldsm4(b0, bB + lrow * ROWB + kb);
            ldsm4(b1, bB + (16 + lrow) * ROWB + kb);
            ldsm4(b2, bB + (32 + lrow) * ROWB + kb);
            ldsm4(b3, bB + (48 + lrow) * ROWB + kb);
            #pragma unroll
            for (int m = 0; m < 2; m++) {
                const uint32_t* af = m ? a1 : a0;
                mma16816(c[m][0], af, b0[0], b0[2]);
                mma16816(c[m][1], af, b0[1], b0[3]);
                mma16816(c[m][2], af, b1[0], b1[2]);
                mma16816(c[m][3], af, b1[1], b1[3]);
                mma16816(c[m][4], af, b2[0], b2[2]);
                mma16816(c[m][5], af, b2[1], b2[3]);
                mma16816(c[m][6], af, b3[0], b3[2]);
                mma16816(c[m][7], af, b3[1], b3[3]);
            }
        }
    }

    const int row0 = mtile * 128 + wm * 32 + (lane >> 2);
    const int col0 = ntile * 128 + wn * 64 + (lane & 3) * 2;
    #pragma unroll
    for (int m = 0; m < 2; m++) {
        #pragma unroll
        for (int n = 0; n < 8; n++) {
            float* p0 = C + (size_t)(row0 + m * 16) * ldc + col0 + n * 8;
            float* p1 = p0 + 8 * (size_t)ldc;
            float2 v0 = make_float2(c[m][n][0], c[m][n][1]);
            float2 v1 = make_float2(c[m][n][2], c[m][n][3]);
            if (accum) {
                float2 o0 = *reinterpret_cast<float2*>(p0);
                float2 o1 = *reinterpret_cast<float2*>(p1);
                v0.x += o0.x; v0.y += o0.y; v1.x += o1.x; v1.y += o1.y;
            }
            *reinterpret_cast<float2*>(p0) = v0;
            *reinterpret_cast<float2*>(p1) = v1;
        }
    }
}

// ---------------- weight split: fp32 [N,K] -> bf16 [N, hi(K)|lo(K)] ----------------
__global__ void __launch_bounds__(256)
split_w_kernel(const float* __restrict__ src, __nv_bfloat16* __restrict__ dst, int K, int total4)
{
    int i = blockIdx.x * 256 + threadIdx.x;
    if (i >= total4) return;
    int k4n = K >> 2;
    int n = i / k4n;
    int k = (i - n * k4n) * 4;
    float4 v = reinterpret_cast<const float4*>(src)[i];
    ushort4 h, l;
    bsplit(v.x, h.x, l.x); bsplit(v.y, h.y, l.y); bsplit(v.z, h.z, l.z); bsplit(v.w, h.w, l.w);
    *reinterpret_cast<ushort4*>(&dst[(size_t)n * 2 * K + k])     = h;
    *reinterpret_cast<ushort4*>(&dst[(size_t)n * 2 * K + K + k]) = l;
}

// ---------------- fp32 SIMT GEMM (x_proj, dt_proj only) ----------------
#define SMPAD 68
__global__ void __launch_bounds__(256)
gemm_kernel(const float* __restrict__ A, int lda,
            const float* __restrict__ B, int ldb,
            float* __restrict__ C, int ldc,
            int M, int N, int Kd,
            const float* __restrict__ bias, int accum)
{
    __shared__ float As[16][SMPAD];
    __shared__ float Bs[16][SMPAD];
    const int tid = threadIdx.x;
    const int tx = tid & 15, ty = tid >> 4;
    const int m0 = blockIdx.y * 64, n0 = blockIdx.x * 64;
    const int lrow = tid >> 2, lk4 = (tid & 3) * 4;
    const int am = m0 + lrow;
    const bool avalid = (am < M);
    const int bn = n0 + lrow;
    const bool bvalid = (bn < N);

    float acc[4][4];
    #pragma unroll
    for (int i = 0; i < 4; i++)
        #pragma unroll
        for (int j = 0; j < 4; j++) acc[i][j] = 0.0f;

    for (int k0 = 0; k0 < Kd; k0 += 16) {
        float4 av = make_float4(0.f,0.f,0.f,0.f), bv = make_float4(0.f,0.f,0.f,0.f);
        if (avalid) av = *reinterpret_cast<const float4*>(&A[(size_t)am * lda + k0 + lk4]);
        if (bvalid) bv = *reinterpret_cast<const float4*>(&B[(size_t)bn * ldb + k0 + lk4]);
        __syncthreads();
        As[lk4+0][lrow]=av.x; As[lk4+1][lrow]=av.y; As[lk4+2][lrow]=av.z; As[lk4+3][lrow]=av.w;
        Bs[lk4+0][lrow]=bv.x; Bs[lk4+1][lrow]=bv.y; Bs[lk4+2][lrow]=bv.z; Bs[lk4+3][lrow]=bv.w;
        __syncthreads();
        #pragma unroll
        for (int k = 0; k < 16; k++) {
            float4 a = *reinterpret_cast<const float4*>(&As[k][ty*4]);
            float4 b = *reinterpret_cast<const float4*>(&Bs[k][tx*4]);
            acc[0][0]+=a.x*b.x; acc[0][1]+=a.x*b.y; acc[0][2]+=a.x*b.z; acc[0][3]+=a.x*b.w;
            acc[1][0]+=a.y*b.x; acc[1][1]+=a.y*b.y; acc[1][2]+=a.y*b.z; acc[1][3]+=a.y*b.w;
            acc[2][0]+=a.z*b.x; acc[2][1]+=a.z*b.y; acc[2][2]+=a.z*b.z; acc[2][3]+=a.z*b.w;
            acc[3][0]+=a.w*b.x; acc[3][1]+=a.w*b.y; acc[3][2]+=a.w*b.z; acc[3][3]+=a.w*b.w;
        }
    }
    #pragma unroll
    for (int i = 0; i < 4; i++) {
        int cm = m0 + ty * 4 + i;
        if (cm >= M) continue;
        #pragma unroll
        for (int j = 0; j < 4; j++) {
            int n = n0 + tx * 4 + j;
            if (n >= N) continue;
            float v = acc[i][j];
            if (bias) v += bias[n];
            size_t ci = (size_t)cm * ldc + n;
            if (accum) C[ci] += v; else C[ci] = v;
        }
    }
}

// ---------------- pipeline kernels ----------------

// embed + norm0: writes g_x (raw) and split bf16 a1
__global__ void __launch_bounds__(256)
embed_rms_kernel(const int* __restrict__ ids, const float* __restrict__ emb,
                 const float* __restrict__ w)
{
    int t = blockIdx.x, tid = threadIdx.x;
    const float* er = emb + (size_t)ids[t] * H_;
    float v[4]; float ss = 0.0f;
    #pragma unroll
    for (int q = 0; q < 4; q++) {
        int i = tid + q * 256;
        v[q] = er[i];
        ss += v[q] * v[q];
        g_x[(size_t)t * H_ + i] = v[q];
    }
    ss = block_reduce_sum_256(ss);
    __shared__ float s_scale;
    if (tid == 0) s_scale = rsqrtf(ss * (1.0f / H_) + EPS_);
    __syncthreads();
    float sc = s_scale;
    #pragma unroll
    for (int q = 0; q < 4; q++) {
        int i = tid + q * 256;
        unsigned short h, l;
        bsplit(v[q] * sc * w[i], h, l);
        g_a1[(size_t)t * 2 * H_ + i]      = __ushort_as_bfloat16(h);
        g_a1[(size_t)t * 2 * H_ + H_ + i] = __ushort_as_bfloat16(l);
    }
}

__global__ void __launch_bounds__(256)
rms_kernel(const float* __restrict__ w)
{
    int t = blockIdx.x, tid = threadIdx.x;
    float v[4]; float ss = 0.0f;
    #pragma unroll
    for (int q = 0; q < 4; q++) { int i = tid + q*256; v[q] = g_x[(size_t)t*H_ + i]; ss += v[q]*v[q]; }
    ss = block_reduce_sum_256(ss);
    __shared__ float s_scale;
    if (tid == 0) s_scale = rsqrtf(ss * (1.0f / H_) + EPS_);
    __syncthreads();
    float sc = s_scale;
    #pragma unroll
    for (int q = 0; q < 4; q++) { int i = tid + q*256; g_xn[(size_t)t*H_ + i] = v[q] * sc * w[i]; }
}

__global__ void __launch_bounds__(256)
conv_silu_kernel(const float* __restrict__ cw, const float* __restrict__ cb)
{
    int idx = blockIdx.x * 256 + threadIdx.x;
    if (idx >= T_ * INNER_) return;
    int t = idx >> 11, c = idx & (INNER_ - 1);
    int b = t >> 10, l = t & (L_ - 1);
    float acc = cb[c];
    #pragma unroll
    for (int k = 0; k < KC_; k++) {
        int ll = l - (KC_ - 1) + k;
        if (ll >= 0) acc += g_proj[(size_t)((b << 10) + ll) * P2_ + c] * cw[c * KC_ + k];
    }
    g_uconv[idx] = siluf(acc);
}

// mamba scan (round-5 verified: writes fp32 g_y only; gate fused OUT — it serialized the recurrence)
__global__ void __launch_bounds__(256)
scan_kernel(const float* __restrict__ a_log, const float* __restrict__ d_param)
{
    int gid = blockIdx.x * 256 + threadIdx.x;
    int grp = gid >> 4, s = gid & 15;
    int b = grp >> 11, c = grp & (INNER_ - 1);
    const float LOG2E = 1.44269504088896340736f;
    float alog2 = -__expf(a_log[c * S_ + s]) * LOG2E;
    float dval = d_param[c];
    float st = 0.0f;
    int tbase = b * L_;
    for (int l = 0; l < L_; l++) {
        int t = tbase + l;
        float draw = g_delta[(size_t)t * INNER_ + c];
        float u = g_uconv[(size_t)t * INNER_ + c];
        float dl = (draw > 20.0f) ? draw : __logf(1.0f + __expf(draw));
        float bt = g_xp[t * XPW_ + DT_ + s];
        float ct = g_xp[t * XPW_ + DT_ + S_ + s];
        float decay = exp2f(dl * alog2);
        st = decay * st + (dl * u) * bt;
        float part = st * ct;
        part += __shfl_xor_sync(0xffffffffu, part, 8);
        part += __shfl_xor_sync(0xffffffffu, part, 4);
        part += __shfl_xor_sync(0xffffffffu, part, 2);
        part += __shfl_xor_sync(0xffffffffu, part, 1);
        if (s == 0) g_y[(size_t)t * INNER_ + c] = part + u * dval;
    }
}

// gu = y * silu(gate) -> split bf16 (separate, fully parallel — round-5 verified)
__global__ void __launch_bounds__(256)
gate_mul_kernel()
{
    int idx = blockIdx.x * 256 + threadIdx.x;
    if (idx >= T_ * INNER_) return;
    int t = idx >> 11, c = idx & (INNER_ - 1);
    float g = g_proj[(size_t)t * P2_ + INNER_ + c];
    float v = g_y[idx] * siluf(g);
    unsigned short h, l;
    bsplit(v, h, l);
    g_a_gu[(size_t)t * 2 * INNER_ + c]          = __ushort_as_bfloat16(h);
    g_a_gu[(size_t)t * 2 * INNER_ + INNER_ + c] = __ushort_as_bfloat16(l);
}

__global__ void __launch_bounds__(256)
router_kernel(const float* __restrict__ rw, const float* __restrict__ rb)
{
    int t = blockIdx.x, tid = threadIdx.x;
    float part[E_];
    #pragma unroll
    for (int e = 0; e < E_; e++) part[e] = 0.0f;
    const float* xr = g_xn + (size_t)t * H_;
    for (int i = tid; i < H_; i += 256) {
        float xv = xr[i];
        #pragma unroll
        for (int e = 0; e < E_; e++) part[e] += xv * rw[e * H_ + i];
    }
    #pragma unroll
    for (int e = 0; e < E_; e++) {
        #pragma unroll
        for (int o = 16; o; o >>= 1) part[e] += __shfl_xor_sync(0xffffffffu, part[e], o);
    }
    __shared__ float red[8][E_];
    int w = tid >> 5;
    if ((tid & 31) == 0) {
        #pragma unroll
        for (int e = 0; e < E_; e++) red[w][e] = part[e];
    }
    __syncthreads();
    if (tid == 0) {
        float lg[E_];
        #pragma unroll
        for (int e = 0; e < E_; e++) {
            float s = 0.0f;
            #pragma unroll
            for (int ww = 0; ww < 8; ww++) s += red[ww][e];
            lg[e] = s + rb[e];
        }
        float mx = lg[0];
        #pragma unroll
        for (int e = 1; e < E_; e++) mx = fmaxf(mx, lg[e]);
        float p[E_], psum = 0.0f;
        #pragma unroll
        for (int e = 0; e < E_; e++) { p[e] = expf(lg[e] - mx); psum += p[e]; }
        float inv = 1.0f / psum;
        #pragma unroll
        for (int e = 0; e < E_; e++) p[e] *= inv;
        int i1 = 0;
        #pragma unroll
        for (int e = 1; e < E_; e++) if (p[e] > p[i1]) i1 = e;
        int i2 = (i1 == 0) ? 1 : 0;
        #pragma unroll
        for (int e = 0; e < E_; e++) if (e != i1 && p[e] > p[i2]) i2 = e;
        g_tope[t*2+0] = i1; g_tope[t*2+1] = i2;
        g_topw[t*2+0] = p[i1]; g_topw[t*2+1] = p[i2];
    }
}

// fused count + offsets + scatter: single CTA, 256 threads
__global__ void __launch_bounds__(256)
route_pack_kernel()
{
    __shared__ int scnt[E_], soff[E_], spos[E_];
    int tid = threadIdx.x;
    if (tid < E_) scnt[tid] = 0;
    __syncthreads();
    for (int t = tid; t < T_; t += 256) {
        atomicAdd(&scnt[g_tope[t*2+0]], 1);
        atomicAdd(&scnt[g_tope[t*2+1]], 1);
    }
    __syncthreads();
    if (tid == 0) {
        int a = 0;
        for (int e = 0; e < E_; e++) {
            soff[e] = a;
            g_offp[e] = a;
            g_cnt[e] = scnt[e];
            int pe = ((scnt[e] + 127) >> 7) << 7;
            int t0 = a >> 7, t1 = (a + pe) >> 7;
            for (int t = t0; t < t1; t++) g_tile_expert[t] = e;
            a += pe;
            spos[e] = 0;
        }
        g_pad_total = a;
        for (int t = a >> 7; t < MT_MOE_; t++) g_tile_expert[t] = 0;
    }
    __syncthreads();
    for (int t = tid; t < T_; t += 256) {
        #pragma unroll
        for (int j = 0; j < 2; j++) {
            int e = g_tope[t*2+j];
            int p = soff[e] + atomicAdd(&spos[e], 1);
            g_pairtok[p] = t;
            g_pairw[p] = g_topw[t*2+j];
            g_pairpos[t*2+j] = p;
        }
    }
}

__global__ void __launch_bounds__(256)
gather_pairs_kernel()
{
    int idx = blockIdx.x * 256 + threadIdx.x;
    int p = idx >> 8;
    int k = (idx & 255) * 4;
    int e = g_tile_expert[p >> 7];
    unsigned lcl = (unsigned)(p - g_offp[e]);
    ushort4 h = make_ushort4(0,0,0,0), l = make_ushort4(0,0,0,0);
    if (lcl < (unsigned)g_cnt[e]) {
        int tok = g_pairtok[p];
        float4 v = reinterpret_cast<const float4*>(g_xn)[(size_t)tok * (H_/4) + (k >> 2)];
        bsplit(v.x, h.x, l.x); bsplit(v.y, h.y, l.y); bsplit(v.z, h.z, l.z); bsplit(v.w, h.w, l.w);
    }
    *reinterpret_cast<ushort4*>(&g_a_pairs[(size_t)p * 2 * H_ + k])      = h;
    *reinterpret_cast<ushort4*>(&g_a_pairs[(size_t)p * 2 * H_ + H_ + k]) = l;
}

__global__ void __launch_bounds__(256)
hidden_split_kernel()
{
    int idx = blockIdx.x * 256 + threadIdx.x;
    if (idx >= NPAD_ * F_) return;
    int p = idx >> 11, f = idx & (F_ - 1);
    if (p >= g_pad_total) return;       // rows beyond padded total are never consumed
    float a = g_h1[(size_t)p * P2_ + f];
    float b2 = g_h1[(size_t)p * P2_ + F_ + f];
    float v = siluf(a) * b2;
    unsigned short h, l;
    bsplit(v, h, l);
    g_a_hid[(size_t)p * 2 * F_ + f]      = __ushort_as_bfloat16(h);
    g_a_hid[(size_t)p * 2 * F_ + F_ + f] = __ushort_as_bfloat16(l);
}

// fused: x += moe combine, then final RMSNorm -> split bf16 a_fin
__global__ void __launch_bounds__(256)
combine_rms_split_kernel(const float* __restrict__ w)
{
    int t = blockIdx.x, tid = threadIdx.x;
    int p0 = g_pairpos[t*2+0], p1 = g_pairpos[t*2+1];
    float w0 = g_pairw[p0], w1 = g_pairw[p1];
    float v[4]; float ss = 0.0f;
    #pragma unroll
    for (int q = 0; q < 4; q++) {
        int i = tid + q*256;
        float xv = g_x[(size_t)t*H_ + i]
                 + w0 * g_moeout[(size_t)p0 * H_ + i]
                 + w1 * g_moeout[(size_t)p1 * H_ + i];
        v[q] = xv;
        ss += xv * xv;
    }
    ss = block_reduce_sum_256(ss);
    __shared__ float s_scale;
    if (tid == 0) s_scale = rsqrtf(ss * (1.0f / H_) + EPS_);
    __syncthreads();
    float sc = s_scale;
    #pragma unroll
    for (int q = 0; q < 4; q++) {
        int i = tid + q*256;
        unsigned short h, l;
        bsplit(v[q] * sc * w[i], h, l);
        g_a_fin[(size_t)t * 2 * H_ + i]      = __ushort_as_bfloat16(h);
        g_a_fin[(size_t)t * 2 * H_ + H_ + i] = __ushort_as_bfloat16(l);
    }
}

// ---------------- host orchestration ----------------
extern "C" void kernel_launch(void* const* d_in, const int* in_sizes, int n_in,
                              void* d_out, int out_size)
{
    const int*   ids   = (const int*)  d_in[0];
    const float* emb   = (const float*)d_in[1];
    const float* n0w   = (const float*)d_in[2];
    const float* inpw  = (const float*)d_in[3];
    const float* convw = (const float*)d_in[4];
    const float* convb = (const float*)d_in[5];
    const float* xpw   = (const float*)d_in[6];
    const float* dtw   = (const float*)d_in[7];
    const float* dtb   = (const float*)d_in[8];
    const float* alog  = (const float*)d_in[9];
    const float* dpar  = (const float*)d_in[10];
    const float* outw  = (const float*)d_in[11];
    const float* n1w   = (const float*)d_in[12];
    const float* rw    = (const float*)d_in[13];
    const float* rb    = (const float*)d_in[14];
    const float* fc1   = (const float*)d_in[15];
    const float* fc2   = (const float*)d_in[16];
    const float* nfw   = (const float*)d_in[17];
    float* out = (float*)d_out;

    float *p_x, *p_xn, *p_proj, *p_uconv, *p_xp, *p_delta, *p_h1, *p_moeout;
    __nv_bfloat16 *p_wa_in, *p_wa_out, *p_wa_fc1, *p_wa_fc2, *p_wa_emb;
    __nv_bfloat16 *p_a1, *p_a_gu, *p_a_pairs, *p_a_hid, *p_a_fin;
    cudaGetSymbolAddress((void**)&p_x,      g_x);
    cudaGetSymbolAddress((void**)&p_xn,     g_xn);
    cudaGetSymbolAddress((void**)&p_proj,   g_proj);
    cudaGetSymbolAddress((void**)&p_uconv,  g_uconv);
    cudaGetSymbolAddress((void**)&p_xp,     g_xp);
    cudaGetSymbolAddress((void**)&p_delta,  g_delta);
    cudaGetSymbolAddress((void**)&p_h1,     g_h1);
    cudaGetSymbolAddress((void**)&p_moeout, g_moeout);
    cudaGetSymbolAddress((void**)&p_wa_in,  g_wa_in);
    cudaGetSymbolAddress((void**)&p_wa_out, g_wa_out);
    cudaGetSymbolAddress((void**)&p_wa_fc1, g_wa_fc1);
    cudaGetSymbolAddress((void**)&p_wa_fc2, g_wa_fc2);
    cudaGetSymbolAddress((void**)&p_wa_emb, g_wa_emb);
    cudaGetSymbolAddress((void**)&p_a1,     g_a1);
    cudaGetSymbolAddress((void**)&p_a_gu,   g_a_gu);
    cudaGetSymbolAddress((void**)&p_a_pairs,g_a_pairs);
    cudaGetSymbolAddress((void**)&p_a_hid,  g_a_hid);
    cudaGetSymbolAddress((void**)&p_a_fin,  g_a_fin);

    cudaFuncSetAttribute(mma_gemm, cudaFuncAttributeMaxDynamicSharedMemorySize, SMEM_MMA);

    // ---- weight hi/lo splits ----
    split_w_kernel<<<(P2_*H_/4 + 255)/256, 256>>>(inpw, p_wa_in,  H_,     P2_*H_/4);
    split_w_kernel<<<(H_*INNER_/4 + 255)/256, 256>>>(outw, p_wa_out, INNER_, H_*INNER_/4);
    split_w_kernel<<<(E_*P2_*H_/4 + 255)/256, 256>>>(fc1, p_wa_fc1, H_, E_*P2_*H_/4);
    split_w_kernel<<<(E_*H_*F_/4 + 255)/256, 256>>>(fc2, p_wa_fc2, F_, E_*H_*F_/4);
    split_w_kernel<<<(V_*H_/4 + 255)/256, 256>>>(emb, p_wa_emb, H_, V_*H_/4);

    // ---- pipeline ----
    embed_rms_kernel<<<T_, 256>>>(ids, emb, n0w);

    // in_proj (mma, 3 phases): [2048 x 4096], K=1024
    {
        dim3 g(T_/128, P2_/128);
        mma_gemm<<<g, 256, SMEM_MMA>>>(p_a1, p_wa_in, p_proj, P2_, H_, 0,  0,  0, 0, 0);
        mma_gemm<<<g, 256, SMEM_MMA>>>(p_a1, p_wa_in, p_proj, P2_, H_, H_, 0,  1, 0, 0);
        mma_gemm<<<g, 256, SMEM_MMA>>>(p_a1, p_wa_in, p_proj, P2_, H_, 0,  H_, 1, 0, 0);
    }

    conv_silu_kernel<<<(T_*INNER_ + 255)/256, 256>>>(convw, convb);

    // x_proj (SIMT): [2048 x 96], K=2048
    gemm_kernel<<<dim3((XPW_+63)/64, T_/64), 256>>>(p_uconv, INNER_, xpw, INNER_, p_xp, XPW_,
                                                    T_, XPW_, INNER_, nullptr, 0);
    // dt_proj (SIMT): [2048 x 2048], K=64
    gemm_kernel<<<dim3(INNER_/64, T_/64), 256>>>(p_xp, XPW_, dtw, DT_, p_delta, INNER_,
                                                 T_, INNER_, DT_, dtb, 0);

    scan_kernel<<<(B_*INNER_*S_)/256, 256>>>(alog, dpar);
    gate_mul_kernel<<<(T_*INNER_ + 255)/256, 256>>>();

    // out_proj (mma, 3 phases, accumulate into residual): [2048 x 1024], K=2048
    {
        dim3 g(T_/128, H_/128);
        mma_gemm<<<g, 256, SMEM_MMA>>>(p_a_gu, p_wa_out, p_x, H_, INNER_, 0,      0,      1, 0, 0);
        mma_gemm<<<g, 256, SMEM_MMA>>>(p_a_gu, p_wa_out, p_x, H_, INNER_, INNER_, 0,      1, 0, 0);
        mma_gemm<<<g, 256, SMEM_MMA>>>(p_a_gu, p_wa_out, p_x, H_, INNER_, 0,      INNER_, 1, 0, 0);
    }

    rms_kernel<<<T_, 256>>>(n1w);

    router_kernel<<<T_, 256>>>(rw, rb);
    route_pack_kernel<<<1, 256>>>();
    gather_pairs_kernel<<<(NPAD_*256 + 255)/256, 256>>>();

    // fc1 (mma, grouped, 3 phases, early-exit past padded total): [<=5120 x 4096], K=1024
    {
        dim3 g(MT_MOE_, P2_/128);
        mma_gemm<<<g, 256, SMEM_MMA>>>(p_a_pairs, p_wa_fc1, p_h1, P2_, H_, 0,  0,  0, 1, P2_);
        mma_gemm<<<g, 256, SMEM_MMA>>>(p_a_pairs, p_wa_fc1, p_h1, P2_, H_, H_, 0,  1, 1, P2_);
        mma_gemm<<<g, 256, SMEM_MMA>>>(p_a_pairs, p_wa_fc1, p_h1, P2_, H_, 0,  H_, 1, 1, P2_);
    }

    hidden_split_kernel<<<(NPAD_*F_ + 255)/256, 256>>>();

    // fc2 (mma, grouped, 3 phases, early-exit): [<=5120 x 1024], K=2048
    {
        dim3 g(MT_MOE_, H_/128);
        mma_gemm<<<g, 256, SMEM_MMA>>>(p_a_hid, p_wa_fc2, p_moeout, H_, F_, 0,  0,  0, 1, H_);
        mma_gemm<<<g, 256, SMEM_MMA>>>(p_a_hid, p_wa_fc2, p_moeout, H_, F_, F_, 0,  1, 1, H_);
        mma_gemm<<<g, 256, SMEM_MMA>>>(p_a_hid, p_wa_fc2, p_moeout, H_, F_, 0,  F_, 1, 1, H_);
    }

    // fused combine + final norm -> a_fin (split)
    combine_rms_split_kernel<<<T_, 256>>>(nfw);

    // logits (mma, 3 phases): [2048 x 32000], K=1024
    {
        dim3 g(T_/128, V_/128);
        mma_gemm<<<g, 256, SMEM_MMA>>>(p_a_fin, p_wa_emb, out, V_, H_, 0,  0,  0, 0, 0);
        mma_gemm<<<g, 256, SMEM_MMA>>>(p_a_fin, p_wa_emb, out, V_, H_, H_, 0,  1, 0, 0);
        mma_gemm<<<g, 256, SMEM_MMA>>>(p_a_fin, p_wa_emb, out, V_, H_, 0,  H_, 1, 0, 0);
    }
}

// round 15
// speedup vs baseline: 1.1287x; 1.0033x over previous
#include <cuda_runtime.h>
#include <cuda_bf16.h>
#include <math.h>
#include <stdint.h>

// ---------------- problem constants ----------------
#define B_      2
#define L_      1024
#define V_      32000
#define H_      1024
#define INNER_  2048
#define S_      16
#define DT_     64
#define KC_     4
#define F_      2048
#define E_      8
#define T_      (B_*L_)          // 2048 tokens
#define P2_     (2*INNER_)       // 4096
#define XPW_    (DT_ + 2*S_)     // 96
#define EPS_    1e-5f
#define NPAD_   5120             // padded token-expert pairs (upper bound)
#define MT_MOE_ (NPAD_/128)      // 40 M-tiles max for MoE GEMMs

// ---------------- scratch (static device memory; no runtime alloc) ----------------
__device__ float g_x     [T_*H_];
__device__ float g_xn    [T_*H_];
__device__ float g_proj  [T_*P2_];
__device__ float g_uconv [T_*INNER_];
__device__ float g_xp    [T_*XPW_];
__device__ float g_delta [T_*INNER_];
__device__ float g_y     [T_*INNER_];
__device__ float g_h1    [(size_t)NPAD_*P2_];
__device__ float g_moeout[(size_t)NPAD_*H_];
__device__ int   g_tope  [T_*2];
__device__ float g_topw  [T_*2];
__device__ int   g_cnt[E_], g_offp[E_];
__device__ int   g_pairtok[NPAD_];
__device__ float g_pairw [NPAD_];
__device__ int   g_pairpos[T_*2];
__device__ int   g_tile_expert[MT_MOE_];
__device__ int   g_pad_total;            // actual padded pair count (multiple of 128)

// bf16 hi|lo split buffers: row layout [hi(0..K-1) | lo(K..2K-1)], width 2K  (round-5 verified)
__device__ __nv_bfloat16 g_wa_in  [(size_t)P2_*2*H_];
__device__ __nv_bfloat16 g_wa_out [(size_t)H_*2*INNER_];
__device__ __nv_bfloat16 g_wa_fc1 [(size_t)E_*P2_*2*H_];
__device__ __nv_bfloat16 g_wa_fc2 [(size_t)E_*H_*2*F_];
__device__ __nv_bfloat16 g_wa_emb [(size_t)V_*2*H_];
__device__ __nv_bfloat16 g_a1     [(size_t)T_*2*H_];      // norm0 output, split
__device__ __nv_bfloat16 g_a_gu   [(size_t)T_*2*INNER_];  // y*silu(gate), split
__device__ __nv_bfloat16 g_a_pairs[(size_t)NPAD_*2*H_];
__device__ __nv_bfloat16 g_a_hid  [(size_t)NPAD_*2*F_];
__device__ __nv_bfloat16 g_a_fin  [(size_t)T_*2*H_];

// ---------------- device helpers ----------------
__device__ __forceinline__ float siluf(float x) { return x / (1.0f + __expf(-x)); }

__device__ __forceinline__ void bsplit(float x, unsigned short& h, unsigned short& l) {
    __nv_bfloat16 hb = __float2bfloat16(x);
    float hr = __bfloat162float(hb);
    __nv_bfloat16 lb = __float2bfloat16(x - hr);
    h = __bfloat16_as_ushort(hb);
    l = __bfloat16_as_ushort(lb);
}

__device__ __forceinline__ float block_reduce_sum_256(float v) {
    #pragma unroll
    for (int o = 16; o; o >>= 1) v += __shfl_xor_sync(0xffffffffu, v, o);
    __shared__ float sm[8];
    int w = threadIdx.x >> 5;
    if ((threadIdx.x & 31) == 0) sm[w] = v;
    __syncthreads();
    float r = (threadIdx.x < 8) ? sm[threadIdx.x] : 0.0f;
    if (threadIdx.x < 32) {
        #pragma unroll
        for (int o = 4; o; o >>= 1) r += __shfl_xor_sync(0xffffffffu, r, o);
    }
    return r;
}

// ---------------- generic PTX (sm_80-compatible) ----------------
__device__ __forceinline__ uint32_t smem_u32(const void* p) {
    uint32_t a;
    asm("{ .reg .u64 t; cvta.to.shared.u64 t, %1; cvt.u32.u64 %0, t; }" : "=r"(a) : "l"(p));
    return a;
}
__device__ __forceinline__ void cp16(uint32_t dst, const void* src) {
    asm volatile("cp.async.cg.shared.global [%0], [%1], 16;" :: "r"(dst), "l"(src) : "memory");
}
#define CP_COMMIT() asm volatile("cp.async.commit_group;" ::: "memory")
#define CP_WAIT1()  asm volatile("cp.async.wait_group 1;" ::: "memory")

__device__ __forceinline__ void ldsm4(uint32_t* r, uint32_t a) {
    asm volatile("ldmatrix.sync.aligned.m8n8.x4.shared.b16 {%0,%1,%2,%3}, [%4];"
                 : "=r"(r[0]), "=r"(r[1]), "=r"(r[2]), "=r"(r[3]) : "r"(a));
}
__device__ __forceinline__ void mma16816(float* c, const uint32_t* a, uint32_t b0, uint32_t b1) {
    asm volatile("mma.sync.aligned.m16n8k16.row.col.f32.bf16.bf16.f32 "
                 "{%0,%1,%2,%3}, {%4,%5,%6,%7}, {%8,%9}, {%0,%1,%2,%3};"
                 : "+f"(c[0]), "+f"(c[1]), "+f"(c[2]), "+f"(c[3])
                 : "r"(a[0]), "r"(a[1]), "r"(a[2]), "r"(a[3]), "r"(b0), "r"(b1));
}

// ---------------- single-phase bf16 tensor GEMM (round-4/5 verified core) ----------------
// ROUND 15 change: __launch_bounds__(256, 2) to allow 2 CTAs/SM (regs capped at 128;
// estimated usage ~120). Covers per-k-tile __syncthreads bubbles with the co-resident CTA.
#define BKROW    40                        // padded smem row (bf16): 80 B
#define ROWB     (BKROW*2)
#define ASIZE    (128*ROWB)                // 10240 B
#define STGB     (2*ASIZE)                 // 20480 B
#define SMEM_MMA (3*STGB)                  // 61440 B

__global__ void __launch_bounds__(256, 2)
mma_gemm(const __nv_bfloat16* __restrict__ A, const __nv_bfloat16* __restrict__ B,
         float* __restrict__ C, int ldc, int Kel, int aoff, int boff,
         int accum, int moe, int nrowsB)
{
    const int mtile = blockIdx.x, ntile = blockIdx.y;
    if (moe && mtile * 128 >= g_pad_total) return;   // skip tiles beyond actual padded pairs

    extern __shared__ __align__(16) char smem[];
    uint32_t sb = smem_u32(smem);
    const int tid = threadIdx.x, lane = tid & 31, wid = tid >> 5;
    const int wm = wid >> 1, wn = wid & 1;
    const int lda = 2 * Kel;
    const int KT = Kel / 32;

    const __nv_bfloat16* Ag = A + (size_t)mtile * 128 * lda + aoff;
    const __nv_bfloat16* Bg = B + (size_t)ntile * 128 * lda + boff
                            + (moe ? (size_t)g_tile_expert[mtile] * nrowsB * lda : 0);

    const int lr = tid >> 2;
    const int lc = (tid & 3) * 8;

    float c[2][8][4];
    #pragma unroll
    for (int i = 0; i < 2; i++)
        #pragma unroll
        for (int j = 0; j < 8; j++)
            #pragma unroll
            for (int q = 0; q < 4; q++) c[i][j][q] = 0.0f;

    auto issue = [&](int kt, int stage) {
        uint32_t sA = sb + stage * STGB;
        uint32_t sB = sA + ASIZE;
        int ko = kt * 32;
        #pragma unroll
        for (int h = 0; h < 2; h++) {
            int row = lr + h * 64;
            cp16(sA + row * ROWB + lc * 2, Ag + (size_t)row * lda + ko + lc);
            cp16(sB + row * ROWB + lc * 2, Bg + (size_t)row * lda + ko + lc);
        }
    };

    issue(0, 0); CP_COMMIT();
    issue(1, 1); CP_COMMIT();

    const int lrow  = (lane & 15);
    const int lcolB = (lane >> 4) * 16;

    for (int kt = 0; kt < KT; kt++) {
        int stage = kt % 3;
        CP_WAIT1();
        __syncthreads();
        if (kt + 2 < KT) issue(kt + 2, (kt + 2) % 3);
        CP_COMMIT();

        uint32_t aB = sb + stage * STGB + (wm * 32) * ROWB;
        uint32_t bB = sb + stage * STGB + ASIZE + (wn * 64) * ROWB;
        #pragma unroll
        for (int ks = 0; ks < 2; ks++) {
            uint32_t kb = ks * 32 + lcolB;
            uint32_t a0[4], a1[4], b0[4], b1[4], b2[4], b3[4];
            ldsm4(a0, aB + lrow * ROWB + kb);
            ldsm4(a1, aB + (16 + lrow) * ROWB + kb);
            ldsm4(b0, bB + lrow * ROWB + kb);
            ldsm4(b1, bB + (16 + lrow) * ROWB + kb);
            ldsm4(b2, bB + (32 + lrow) * ROWB + kb);
            ldsm4(b3, bB + (48 + lrow) * ROWB + kb);
            #pragma unroll
            for (int m = 0; m < 2; m++) {
                const uint32_t* af = m ? a1 : a0;
                mma16816(c[m][0], af, b0[0], b0[2]);
                mma16816(c[m][1], af, b0[1], b0[3]);
                mma16816(c[m][2], af, b1[0], b1[2]);
                mma16816(c[m][3], af, b1[1], b1[3]);
                mma16816(c[m][4], af, b2[0], b2[2]);
                mma16816(c[m][5], af, b2[1], b2[3]);
                mma16816(c[m][6], af, b3[0], b3[2]);
                mma16816(c[m][7], af, b3[1], b3[3]);
            }
        }
    }

    const int row0 = mtile * 128 + wm * 32 + (lane >> 2);
    const int col0 = ntile * 128 + wn * 64 + (lane & 3) * 2;
    #pragma unroll
    for (int m = 0; m < 2; m++) {
        #pragma unroll
        for (int n = 0; n < 8; n++) {
            float* p0 = C + (size_t)(row0 + m * 16) * ldc + col0 + n * 8;
            float* p1 = p0 + 8 * (size_t)ldc;
            float2 v0 = make_float2(c[m][n][0], c[m][n][1]);
            float2 v1 = make_float2(c[m][n][2], c[m][n][3]);
            if (accum) {
                float2 o0 = *reinterpret_cast<float2*>(p0);
                float2 o1 = *reinterpret_cast<float2*>(p1);
                v0.x += o0.x; v0.y += o0.y; v1.x += o1.x; v1.y += o1.y;
            }
            *reinterpret_cast<float2*>(p0) = v0;
            *reinterpret_cast<float2*>(p1) = v1;
        }
    }
}

// ---------------- weight split: fp32 [N,K] -> bf16 [N, hi(K)|lo(K)] ----------------
__global__ void __launch_bounds__(256)
split_w_kernel(const float* __restrict__ src, __nv_bfloat16* __restrict__ dst, int K, int total4)
{
    int i = blockIdx.x * 256 + threadIdx.x;
    if (i >= total4) return;
    int k4n = K >> 2;
    int n = i / k4n;
    int k = (i - n * k4n) * 4;
    float4 v = reinterpret_cast<const float4*>(src)[i];
    ushort4 h, l;
    bsplit(v.x, h.x, l.x); bsplit(v.y, h.y, l.y); bsplit(v.z, h.z, l.z); bsplit(v.w, h.w, l.w);
    *reinterpret_cast<ushort4*>(&dst[(size_t)n * 2 * K + k])     = h;
    *reinterpret_cast<ushort4*>(&dst[(size_t)n * 2 * K + K + k]) = l;
}

// ---------------- fp32 SIMT GEMM (x_proj, dt_proj only) ----------------
#define SMPAD 68
__global__ void __launch_bounds__(256)
gemm_kernel(const float* __restrict__ A, int lda,
            const float* __restrict__ B, int ldb,
            float* __restrict__ C, int ldc,
            int M, int N, int Kd,
            const float* __restrict__ bias, int accum)
{
    __shared__ float As[16][SMPAD];
    __shared__ float Bs[16][SMPAD];
    const int tid = threadIdx.x;
    const int tx = tid & 15, ty = tid >> 4;
    const int m0 = blockIdx.y * 64, n0 = blockIdx.x * 64;
    const int lrow = tid >> 2, lk4 = (tid & 3) * 4;
    const int am = m0 + lrow;
    const bool avalid = (am < M);
    const int bn = n0 + lrow;
    const bool bvalid = (bn < N);

    float acc[4][4];
    #pragma unroll
    for (int i = 0; i < 4; i++)
        #pragma unroll
        for (int j = 0; j < 4; j++) acc[i][j] = 0.0f;

    for (int k0 = 0; k0 < Kd; k0 += 16) {
        float4 av = make_float4(0.f,0.f,0.f,0.f), bv = make_float4(0.f,0.f,0.f,0.f);
        if (avalid) av = *reinterpret_cast<const float4*>(&A[(size_t)am * lda + k0 + lk4]);
        if (bvalid) bv = *reinterpret_cast<const float4*>(&B[(size_t)bn * ldb + k0 + lk4]);
        __syncthreads();
        As[lk4+0][lrow]=av.x; As[lk4+1][lrow]=av.y; As[lk4+2][lrow]=av.z; As[lk4+3][lrow]=av.w;
        Bs[lk4+0][lrow]=bv.x; Bs[lk4+1][lrow]=bv.y; Bs[lk4+2][lrow]=bv.z; Bs[lk4+3][lrow]=bv.w;
        __syncthreads();
        #pragma unroll
        for (int k = 0; k < 16; k++) {
            float4 a = *reinterpret_cast<const float4*>(&As[k][ty*4]);
            float4 b = *reinterpret_cast<const float4*>(&Bs[k][tx*4]);
            acc[0][0]+=a.x*b.x; acc[0][1]+=a.x*b.y; acc[0][2]+=a.x*b.z; acc[0][3]+=a.x*b.w;
            acc[1][0]+=a.y*b.x; acc[1][1]+=a.y*b.y; acc[1][2]+=a.y*b.z; acc[1][3]+=a.y*b.w;
            acc[2][0]+=a.z*b.x; acc[2][1]+=a.z*b.y; acc[2][2]+=a.z*b.z; acc[2][3]+=a.z*b.w;
            acc[3][0]+=a.w*b.x; acc[3][1]+=a.w*b.y; acc[3][2]+=a.w*b.z; acc[3][3]+=a.w*b.w;
        }
    }
    #pragma unroll
    for (int i = 0; i < 4; i++) {
        int cm = m0 + ty * 4 + i;
        if (cm >= M) continue;
        #pragma unroll
        for (int j = 0; j < 4; j++) {
            int n = n0 + tx * 4 + j;
            if (n >= N) continue;
            float v = acc[i][j];
            if (bias) v += bias[n];
            size_t ci = (size_t)cm * ldc + n;
            if (accum) C[ci] += v; else C[ci] = v;
        }
    }
}

// ---------------- pipeline kernels ----------------

// embed + norm0: writes g_x (raw) and split bf16 a1
__global__ void __launch_bounds__(256)
embed_rms_kernel(const int* __restrict__ ids, const float* __restrict__ emb,
                 const float* __restrict__ w)
{
    int t = blockIdx.x, tid = threadIdx.x;
    const float* er = emb + (size_t)ids[t] * H_;
    float v[4]; float ss = 0.0f;
    #pragma unroll
    for (int q = 0; q < 4; q++) {
        int i = tid + q * 256;
        v[q] = er[i];
        ss += v[q] * v[q];
        g_x[(size_t)t * H_ + i] = v[q];
    }
    ss = block_reduce_sum_256(ss);
    __shared__ float s_scale;
    if (tid == 0) s_scale = rsqrtf(ss * (1.0f / H_) + EPS_);
    __syncthreads();
    float sc = s_scale;
    #pragma unroll
    for (int q = 0; q < 4; q++) {
        int i = tid + q * 256;
        unsigned short h, l;
        bsplit(v[q] * sc * w[i], h, l);
        g_a1[(size_t)t * 2 * H_ + i]      = __ushort_as_bfloat16(h);
        g_a1[(size_t)t * 2 * H_ + H_ + i] = __ushort_as_bfloat16(l);
    }
}

__global__ void __launch_bounds__(256)
rms_kernel(const float* __restrict__ w)
{
    int t = blockIdx.x, tid = threadIdx.x;
    float v[4]; float ss = 0.0f;
    #pragma unroll
    for (int q = 0; q < 4; q++) { int i = tid + q*256; v[q] = g_x[(size_t)t*H_ + i]; ss += v[q]*v[q]; }
    ss = block_reduce_sum_256(ss);
    __shared__ float s_scale;
    if (tid == 0) s_scale = rsqrtf(ss * (1.0f / H_) + EPS_);
    __syncthreads();
    float sc = s_scale;
    #pragma unroll
    for (int q = 0; q < 4; q++) { int i = tid + q*256; g_xn[(size_t)t*H_ + i] = v[q] * sc * w[i]; }
}

__global__ void __launch_bounds__(256)
conv_silu_kernel(const float* __restrict__ cw, const float* __restrict__ cb)
{
    int idx = blockIdx.x * 256 + threadIdx.x;
    if (idx >= T_ * INNER_) return;
    int t = idx >> 11, c = idx & (INNER_ - 1);
    int b = t >> 10, l = t & (L_ - 1);
    float acc = cb[c];
    #pragma unroll
    for (int k = 0; k < KC_; k++) {
        int ll = l - (KC_ - 1) + k;
        if (ll >= 0) acc += g_proj[(size_t)((b << 10) + ll) * P2_ + c] * cw[c * KC_ + k];
    }
    g_uconv[idx] = siluf(acc);
}

// mamba scan (round-5 verified)
__global__ void __launch_bounds__(256)
scan_kernel(const float* __restrict__ a_log, const float* __restrict__ d_param)
{
    int gid = blockIdx.x * 256 + threadIdx.x;
    int grp = gid >> 4, s = gid & 15;
    int b = grp >> 11, c = grp & (INNER_ - 1);
    const float LOG2E = 1.44269504088896340736f;
    float alog2 = -__expf(a_log[c * S_ + s]) * LOG2E;
    float dval = d_param[c];
    float st = 0.0f;
    int tbase = b * L_;
    for (int l = 0; l < L_; l++) {
        int t = tbase + l;
        float draw = g_delta[(size_t)t * INNER_ + c];
        float u = g_uconv[(size_t)t * INNER_ + c];
        float dl = (draw > 20.0f) ? draw : __logf(1.0f + __expf(draw));
        float bt = g_xp[t * XPW_ + DT_ + s];
        float ct = g_xp[t * XPW_ + DT_ + S_ + s];
        float decay = exp2f(dl * alog2);
        st = decay * st + (dl * u) * bt;
        float part = st * ct;
        part += __shfl_xor_sync(0xffffffffu, part, 8);
        part += __shfl_xor_sync(0xffffffffu, part, 4);
        part += __shfl_xor_sync(0xffffffffu, part, 2);
        part += __shfl_xor_sync(0xffffffffu, part, 1);
        if (s == 0) g_y[(size_t)t * INNER_ + c] = part + u * dval;
    }
}

// gu = y * silu(gate) -> split bf16 (separate, fully parallel)
__global__ void __launch_bounds__(256)
gate_mul_kernel()
{
    int idx = blockIdx.x * 256 + threadIdx.x;
    if (idx >= T_ * INNER_) return;
    int t = idx >> 11, c = idx & (INNER_ - 1);
    float g = g_proj[(size_t)t * P2_ + INNER_ + c];
    float v = g_y[idx] * siluf(g);
    unsigned short h, l;
    bsplit(v, h, l);
    g_a_gu[(size_t)t * 2 * INNER_ + c]          = __ushort_as_bfloat16(h);
    g_a_gu[(size_t)t * 2 * INNER_ + INNER_ + c] = __ushort_as_bfloat16(l);
}

__global__ void __launch_bounds__(256)
router_kernel(const float* __restrict__ rw, const float* __restrict__ rb)
{
    int t = blockIdx.x, tid = threadIdx.x;
    float part[E_];
    #pragma unroll
    for (int e = 0; e < E_; e++) part[e] = 0.0f;
    const float* xr = g_xn + (size_t)t * H_;
    for (int i = tid; i < H_; i += 256) {
        float xv = xr[i];
        #pragma unroll
        for (int e = 0; e < E_; e++) part[e] += xv * rw[e * H_ + i];
    }
    #pragma unroll
    for (int e = 0; e < E_; e++) {
        #pragma unroll
        for (int o = 16; o; o >>= 1) part[e] += __shfl_xor_sync(0xffffffffu, part[e], o);
    }
    __shared__ float red[8][E_];
    int w = tid >> 5;
    if ((tid & 31) == 0) {
        #pragma unroll
        for (int e = 0; e < E_; e++) red[w][e] = part[e];
    }
    __syncthreads();
    if (tid == 0) {
        float lg[E_];
        #pragma unroll
        for (int e = 0; e < E_; e++) {
            float s = 0.0f;
            #pragma unroll
            for (int ww = 0; ww < 8; ww++) s += red[ww][e];
            lg[e] = s + rb[e];
        }
        float mx = lg[0];
        #pragma unroll
        for (int e = 1; e < E_; e++) mx = fmaxf(mx, lg[e]);
        float p[E_], psum = 0.0f;
        #pragma unroll
        for (int e = 0; e < E_; e++) { p[e] = expf(lg[e] - mx); psum += p[e]; }
        float inv = 1.0f / psum;
        #pragma unroll
        for (int e = 0; e < E_; e++) p[e] *= inv;
        int i1 = 0;
        #pragma unroll
        for (int e = 1; e < E_; e++) if (p[e] > p[i1]) i1 = e;
        int i2 = (i1 == 0) ? 1 : 0;
        #pragma unroll
        for (int e = 0; e < E_; e++) if (e != i1 && p[e] > p[i2]) i2 = e;
        g_tope[t*2+0] = i1; g_tope[t*2+1] = i2;
        g_topw[t*2+0] = p[i1]; g_topw[t*2+1] = p[i2];
    }
}

// fused count + offsets + scatter: single CTA, 256 threads
__global__ void __launch_bounds__(256)
route_pack_kernel()
{
    __shared__ int scnt[E_], soff[E_], spos[E_];
    int tid = threadIdx.x;
    if (tid < E_) scnt[tid] = 0;
    __syncthreads();
    for (int t = tid; t < T_; t += 256) {
        atomicAdd(&scnt[g_tope[t*2+0]], 1);
        atomicAdd(&scnt[g_tope[t*2+1]], 1);
    }
    __syncthreads();
    if (tid == 0) {
        int a = 0;
        for (int e = 0; e < E_; e++) {
            soff[e] = a;
            g_offp[e] = a;
            g_cnt[e] = scnt[e];
            int pe = ((scnt[e] + 127) >> 7) << 7;
            int t0 = a >> 7, t1 = (a + pe) >> 7;
            for (int t = t0; t < t1; t++) g_tile_expert[t] = e;
            a += pe;
            spos[e] = 0;
        }
        g_pad_total = a;
        for (int t = a >> 7; t < MT_MOE_; t++) g_tile_expert[t] = 0;
    }
    __syncthreads();
    for (int t = tid; t < T_; t += 256) {
        #pragma unroll
        for (int j = 0; j < 2; j++) {
            int e = g_tope[t*2+j];
            int p = soff[e] + atomicAdd(&spos[e], 1);
            g_pairtok[p] = t;
            g_pairw[p] = g_topw[t*2+j];
            g_pairpos[t*2+j] = p;
        }
    }
}

__global__ void __launch_bounds__(256)
gather_pairs_kernel()
{
    int idx = blockIdx.x * 256 + threadIdx.x;
    int p = idx >> 8;
    int k = (idx & 255) * 4;
    int e = g_tile_expert[p >> 7];
    unsigned lcl = (unsigned)(p - g_offp[e]);
    ushort4 h = make_ushort4(0,0,0,0), l = make_ushort4(0,0,0,0);
    if (lcl < (unsigned)g_cnt[e]) {
        int tok = g_pairtok[p];
        float4 v = reinterpret_cast<const float4*>(g_xn)[(size_t)tok * (H_/4) + (k >> 2)];
        bsplit(v.x, h.x, l.x); bsplit(v.y, h.y, l.y); bsplit(v.z, h.z, l.z); bsplit(v.w, h.w, l.w);
    }
    *reinterpret_cast<ushort4*>(&g_a_pairs[(size_t)p * 2 * H_ + k])      = h;
    *reinterpret_cast<ushort4*>(&g_a_pairs[(size_t)p * 2 * H_ + H_ + k]) = l;
}

__global__ void __launch_bounds__(256)
hidden_split_kernel()
{
    int idx = blockIdx.x * 256 + threadIdx.x;
    if (idx >= NPAD_ * F_) return;
    int p = idx >> 11, f = idx & (F_ - 1);
    if (p >= g_pad_total) return;       // rows beyond padded total are never consumed
    float a = g_h1[(size_t)p * P2_ + f];
    float b2 = g_h1[(size_t)p * P2_ + F_ + f];
    float v = siluf(a) * b2;
    unsigned short h, l;
    bsplit(v, h, l);
    g_a_hid[(size_t)p * 2 * F_ + f]      = __ushort_as_bfloat16(h);
    g_a_hid[(size_t)p * 2 * F_ + F_ + f] = __ushort_as_bfloat16(l);
}

// fused: x += moe combine, then final RMSNorm -> split bf16 a_fin
__global__ void __launch_bounds__(256)
combine_rms_split_kernel(const float* __restrict__ w)
{
    int t = blockIdx.x, tid = threadIdx.x;
    int p0 = g_pairpos[t*2+0], p1 = g_pairpos[t*2+1];
    float w0 = g_pairw[p0], w1 = g_pairw[p1];
    float v[4]; float ss = 0.0f;
    #pragma unroll
    for (int q = 0; q < 4; q++) {
        int i = tid + q*256;
        float xv = g_x[(size_t)t*H_ + i]
                 + w0 * g_moeout[(size_t)p0 * H_ + i]
                 + w1 * g_moeout[(size_t)p1 * H_ + i];
        v[q] = xv;
        ss += xv * xv;
    }
    ss = block_reduce_sum_256(ss);
    __shared__ float s_scale;
    if (tid == 0) s_scale = rsqrtf(ss * (1.0f / H_) + EPS_);
    __syncthreads();
    float sc = s_scale;
    #pragma unroll
    for (int q = 0; q < 4; q++) {
        int i = tid + q*256;
        unsigned short h, l;
        bsplit(v[q] * sc * w[i], h, l);
        g_a_fin[(size_t)t * 2 * H_ + i]      = __ushort_as_bfloat16(h);
        g_a_fin[(size_t)t * 2 * H_ + H_ + i] = __ushort_as_bfloat16(l);
    }
}

// ---------------- host orchestration ----------------
extern "C" void kernel_launch(void* const* d_in, const int* in_sizes, int n_in,
                              void* d_out, int out_size)
{
    const int*   ids   = (const int*)  d_in[0];
    const float* emb   = (const float*)d_in[1];
    const float* n0w   = (const float*)d_in[2];
    const float* inpw  = (const float*)d_in[3];
    const float* convw = (const float*)d_in[4];
    const float* convb = (const float*)d_in[5];
    const float* xpw   = (const float*)d_in[6];
    const float* dtw   = (const float*)d_in[7];
    const float* dtb   = (const float*)d_in[8];
    const float* alog  = (const float*)d_in[9];
    const float* dpar  = (const float*)d_in[10];
    const float* outw  = (const float*)d_in[11];
    const float* n1w   = (const float*)d_in[12];
    const float* rw    = (const float*)d_in[13];
    const float* rb    = (const float*)d_in[14];
    const float* fc1   = (const float*)d_in[15];
    const float* fc2   = (const float*)d_in[16];
    const float* nfw   = (const float*)d_in[17];
    float* out = (float*)d_out;

    float *p_x, *p_xn, *p_proj, *p_uconv, *p_xp, *p_delta, *p_h1, *p_moeout;
    __nv_bfloat16 *p_wa_in, *p_wa_out, *p_wa_fc1, *p_wa_fc2, *p_wa_emb;
    __nv_bfloat16 *p_a1, *p_a_gu, *p_a_pairs, *p_a_hid, *p_a_fin;
    cudaGetSymbolAddress((void**)&p_x,      g_x);
    cudaGetSymbolAddress((void**)&p_xn,     g_xn);
    cudaGetSymbolAddress((void**)&p_proj,   g_proj);
    cudaGetSymbolAddress((void**)&p_uconv,  g_uconv);
    cudaGetSymbolAddress((void**)&p_xp,     g_xp);
    cudaGetSymbolAddress((void**)&p_delta,  g_delta);
    cudaGetSymbolAddress((void**)&p_h1,     g_h1);
    cudaGetSymbolAddress((void**)&p_moeout, g_moeout);
    cudaGetSymbolAddress((void**)&p_wa_in,  g_wa_in);
    cudaGetSymbolAddress((void**)&p_wa_out, g_wa_out);
    cudaGetSymbolAddress((void**)&p_wa_fc1, g_wa_fc1);
    cudaGetSymbolAddress((void**)&p_wa_fc2, g_wa_fc2);
    cudaGetSymbolAddress((void**)&p_wa_emb, g_wa_emb);
    cudaGetSymbolAddress((void**)&p_a1,     g_a1);
    cudaGetSymbolAddress((void**)&p_a_gu,   g_a_gu);
    cudaGetSymbolAddress((void**)&p_a_pairs,g_a_pairs);
    cudaGetSymbolAddress((void**)&p_a_hid,  g_a_hid);
    cudaGetSymbolAddress((void**)&p_a_fin,  g_a_fin);

    cudaFuncSetAttribute(mma_gemm, cudaFuncAttributeMaxDynamicSharedMemorySize, SMEM_MMA);

    // ---- weight hi/lo splits ----
    split_w_kernel<<<(P2_*H_/4 + 255)/256, 256>>>(inpw, p_wa_in,  H_,     P2_*H_/4);
    split_w_kernel<<<(H_*INNER_/4 + 255)/256, 256>>>(outw, p_wa_out, INNER_, H_*INNER_/4);
    split_w_kernel<<<(E_*P2_*H_/4 + 255)/256, 256>>>(fc1, p_wa_fc1, H_, E_*P2_*H_/4);
    split_w_kernel<<<(E_*H_*F_/4 + 255)/256, 256>>>(fc2, p_wa_fc2, F_, E_*H_*F_/4);
    split_w_kernel<<<(V_*H_/4 + 255)/256, 256>>>(emb, p_wa_emb, H_, V_*H_/4);

    // ---- pipeline ----
    embed_rms_kernel<<<T_, 256>>>(ids, emb, n0w);

    // in_proj (mma, 3 phases): [2048 x 4096], K=1024
    {
        dim3 g(T_/128, P2_/128);
        mma_gemm<<<g, 256, SMEM_MMA>>>(p_a1, p_wa_in, p_proj, P2_, H_, 0,  0,  0, 0, 0);
        mma_gemm<<<g, 256, SMEM_MMA>>>(p_a1, p_wa_in, p_proj, P2_, H_, H_, 0,  1, 0, 0);
        mma_gemm<<<g, 256, SMEM_MMA>>>(p_a1, p_wa_in, p_proj, P2_, H_, 0,  H_, 1, 0, 0);
    }

    conv_silu_kernel<<<(T_*INNER_ + 255)/256, 256>>>(convw, convb);

    // x_proj (SIMT): [2048 x 96], K=2048
    gemm_kernel<<<dim3((XPW_+63)/64, T_/64), 256>>>(p_uconv, INNER_, xpw, INNER_, p_xp, XPW_,
                                                    T_, XPW_, INNER_, nullptr, 0);
    // dt_proj (SIMT): [2048 x 2048], K=64
    gemm_kernel<<<dim3(INNER_/64, T_/64), 256>>>(p_xp, XPW_, dtw, DT_, p_delta, INNER_,
                                                 T_, INNER_, DT_, dtb, 0);

    scan_kernel<<<(B_*INNER_*S_)/256, 256>>>(alog, dpar);
    gate_mul_kernel<<<(T_*INNER_ + 255)/256, 256>>>();

    // out_proj (mma, 3 phases, accumulate into residual): [2048 x 1024], K=2048
    {
        dim3 g(T_/128, H_/128);
        mma_gemm<<<g, 256, SMEM_MMA>>>(p_a_gu, p_wa_out, p_x, H_, INNER_, 0,      0,      1, 0, 0);
        mma_gemm<<<g, 256, SMEM_MMA>>>(p_a_gu, p_wa_out, p_x, H_, INNER_, INNER_, 0,      1, 0, 0);
        mma_gemm<<<g, 256, SMEM_MMA>>>(p_a_gu, p_wa_out, p_x, H_, INNER_, 0,      INNER_, 1, 0, 0);
    }

    rms_kernel<<<T_, 256>>>(n1w);

    router_kernel<<<T_, 256>>>(rw, rb);
    route_pack_kernel<<<1, 256>>>();
    gather_pairs_kernel<<<(NPAD_*256 + 255)/256, 256>>>();

    // fc1 (mma, grouped, 3 phases, early-exit past padded total): [<=5120 x 4096], K=1024
    {
        dim3 g(MT_MOE_, P2_/128);
        mma_gemm<<<g, 256, SMEM_MMA>>>(p_a_pairs, p_wa_fc1, p_h1, P2_, H_, 0,  0,  0, 1, P2_);
        mma_gemm<<<g, 256, SMEM_MMA>>>(p_a_pairs, p_wa_fc1, p_h1, P2_, H_, H_, 0,  1, 1, P2_);
        mma_gemm<<<g, 256, SMEM_MMA>>>(p_a_pairs, p_wa_fc1, p_h1, P2_, H_, 0,  H_, 1, 1, P2_);
    }

    hidden_split_kernel<<<(NPAD_*F_ + 255)/256, 256>>>();

    // fc2 (mma, grouped, 3 phases, early-exit): [<=5120 x 1024], K=2048
    {
        dim3 g(MT_MOE_, H_/128);
        mma_gemm<<<g, 256, SMEM_MMA>>>(p_a_hid, p_wa_fc2, p_moeout, H_, F_, 0,  0,  0, 1, H_);
        mma_gemm<<<g, 256, SMEM_MMA>>>(p_a_hid, p_wa_fc2, p_moeout, H_, F_, F_, 0,  1, 1, H_);
        mma_gemm<<<g, 256, SMEM_MMA>>>(p_a_hid, p_wa_fc2, p_moeout, H_, F_, 0,  F_, 1, 1, H_);
    }

    // fused combine + final norm -> a_fin (split)
    combine_rms_split_kernel<<<T_, 256>>>(nfw);

    // logits (mma, 3 phases): [2048 x 32000], K=1024
    {
        dim3 g(T_/128, V_/128);
        mma_gemm<<<g, 256, SMEM_MMA>>>(p_a_fin, p_wa_emb, out, V_, H_, 0,  0,  0, 0, 0);
        mma_gemm<<<g, 256, SMEM_MMA>>>(p_a_fin, p_wa_emb, out, V_, H_, H_, 0,  1, 0, 0);
        mma_gemm<<<g, 256, SMEM_MMA>>>(p_a_fin, p_wa_emb, out, V_, H_, 0,  H_, 1, 0, 0);
    }
}